// round 11
// baseline (speedup 1.0000x reference)
#include <cuda_runtime.h>
#include <cuda_bf16.h>
#include <cstdint>
#include <stdint.h>
#include <math.h>

#define B_    4
#define N_    4096
#define C_    512
#define H_    16
#define D_    32
#define M_    (B_*N_)      // 16384
#define KDIM  512
#define NOUT  1024
#define NCHUNK 8
#define CHUNK (N_/NCHUNK)  // 512

// -------- scratch (device globals; no allocations allowed) --------
__device__ float  g_q[M_*C_];                      // elu(q)+1
__device__ float  g_k[M_*C_];                      // elu(k)+1
__device__ float2 g_cs[N_*256];                    // rope cos/sin table
__device__ float  g_kvp[NCHUNK*B_*H_*D_*D_];       // partial kv
__device__ float  g_ksp[NCHUNK*B_*H_*D_];          // partial k sums
__device__ float  g_kv[B_*H_*D_*D_];               // kv (scaled by 1/N)
__device__ float  g_km[B_*H_*D_];                  // kmean
// bf16x3 split operands for the tensor-core GEMM
__device__ __nv_bfloat16 g_xhi[M_*KDIM];
__device__ __nv_bfloat16 g_xlo[M_*KDIM];
__device__ __nv_bfloat16 g_wthi[NOUT*KDIM];        // W^T [n][k]
__device__ __nv_bfloat16 g_wtlo[NOUT*KDIM];

// ============================================================
// helpers (base-ISA only: ldmatrix / mma.sync / cp.async)
// ============================================================
__device__ __forceinline__ uint32_t smem_u32(const void* p) {
    uint32_t a;
    asm("{ .reg .u64 t; cvta.to.shared.u64 t, %1; cvt.u32.u64 %0, t; }"
        : "=r"(a) : "l"(p));
    return a;
}
#define CP_ASYNC16(dst, src) \
    asm volatile("cp.async.cg.shared.global [%0], [%1], 16;" :: "r"(dst), "l"(src))
#define CP_COMMIT() asm volatile("cp.async.commit_group;" ::: "memory")
#define LDSM4(r0, r1, r2, r3, addr) \
    asm volatile("ldmatrix.sync.aligned.m8n8.x4.shared.b16 {%0,%1,%2,%3}, [%4];" \
        : "=r"(r0), "=r"(r1), "=r"(r2), "=r"(r3) : "r"(addr))
#define MMA16816(d, a, b) \
    asm volatile("mma.sync.aligned.m16n8k16.row.col.f32.bf16.bf16.f32 " \
        "{%0,%1,%2,%3}, {%4,%5,%6,%7}, {%8,%9}, {%0,%1,%2,%3};" \
        : "+f"((d)[0]), "+f"((d)[1]), "+f"((d)[2]), "+f"((d)[3]) \
        : "r"((a)[0]), "r"((a)[1]), "r"((a)[2]), "r"((a)[3]), \
          "r"((b)[0]), "r"((b)[1]))

// ============================================================
// RoPE table: emulate JAX fp32 theta & ang, accurate sincos.
// ============================================================
__global__ void rope_table_k() {
    int idx = blockIdx.x * 256 + threadIdx.x;     // N_*256 entries
    int n = idx >> 8;
    int j = idx & 255;
    double theta_d = exp((double)j * (-9.210340371976184 / 256.0));
    float  theta   = (float)theta_d;
    float  ang     = (float)n * theta;            // fp32 multiply, like JAX
    double a = (double)ang;
    double kq = rint(a * 0.15915494309189535);    // 1/(2*pi)
    double r  = fma(-kq, 6.283185307179586, a);
    float s, c;
    sincosf((float)r, &s, &c);
    g_cs[idx] = make_float2(c, s);
}

// ============================================================
// bf16 hi/lo splits
// ============================================================
__global__ void split_x_k(const float* __restrict__ X) {
    int i = blockIdx.x * 256 + threadIdx.x;       // float4 index, M_*KDIM/4 total
    float4 v = ((const float4*)X)[i];
    __nv_bfloat16 h0 = __float2bfloat16(v.x), h1 = __float2bfloat16(v.y);
    __nv_bfloat16 h2 = __float2bfloat16(v.z), h3 = __float2bfloat16(v.w);
    __nv_bfloat16 l0 = __float2bfloat16(v.x - __bfloat162float(h0));
    __nv_bfloat16 l1 = __float2bfloat16(v.y - __bfloat162float(h1));
    __nv_bfloat16 l2 = __float2bfloat16(v.z - __bfloat162float(h2));
    __nv_bfloat16 l3 = __float2bfloat16(v.w - __bfloat162float(h3));
    __nv_bfloat162* ph = (__nv_bfloat162*)(g_xhi + 4 * (size_t)i);
    __nv_bfloat162* pl = (__nv_bfloat162*)(g_xlo + 4 * (size_t)i);
    ph[0] = __nv_bfloat162(h0, h1); ph[1] = __nv_bfloat162(h2, h3);
    pl[0] = __nv_bfloat162(l0, l1); pl[1] = __nv_bfloat162(l2, l3);
}

__global__ void split_wt_k(const float* __restrict__ W) {
    int i = blockIdx.x * 256 + threadIdx.x;       // NOUT*KDIM total
    int n = i >> 9, k = i & 511;
    float v = W[(size_t)k * NOUT + n];
    __nv_bfloat16 h = __float2bfloat16(v);
    g_wthi[i] = h;
    g_wtlo[i] = __float2bfloat16(v - __bfloat162float(h));
}

// ============================================================
// HMMA GEMM: qk = x @ Wqk + b via bf16x3 (K_eff = 1536),
// CTA tile 128x256, warp tile 64x64 (2x4 warps), BK=64,
// 3-stage cp.async pipeline, 1 CTA/SM.
// ============================================================
#define BK       64
#define LDS_ROW  72                    // 64 halves + 8 pad
#define A_TILE_B (128 * LDS_ROW * 2)   // 18432
#define B_TILE_B (256 * LDS_ROW * 2)   // 36864
#define STAGE_B  (A_TILE_B + B_TILE_B) // 55296
#define GEMM_SMEM (3 * STAGE_B)        // 165888

__global__ __launch_bounds__(256, 1) void gemm_hmma_k(const float* __restrict__ bias)
{
    extern __shared__ __align__(16) char sm[];
    uint32_t smb = smem_u32(sm);

    int tid = threadIdx.x;
    int lane = tid & 31, wid = tid >> 5;
    int warp_m = wid & 1;         // 2 x 64 rows
    int warp_n = wid >> 1;        // 4 x 64 cols
    int mbase = blockIdx.y * 128;
    int nblk  = blockIdx.x * 256;

    float acc[4][8][4];
    #pragma unroll
    for (int i = 0; i < 4; i++)
        #pragma unroll
        for (int j = 0; j < 8; j++)
            #pragma unroll
            for (int r = 0; r < 4; r++) acc[i][j][r] = 0.f;

    // 24 chunks of BK=64; pass = c>>3 in {0:(hi,hi), 1:(hi,lo), 2:(lo,hi)}
    auto prefetch = [&](int c, int s) {
        int pass = c >> 3;
        int kc   = (c & 7) * BK;
        const __nv_bfloat16* Ap = (pass < 2) ? g_xhi : g_xlo;
        const __nv_bfloat16* Bp = (pass == 1) ? g_wtlo : g_wthi;
        uint32_t ab = smb + s * STAGE_B;
        uint32_t bb = ab + A_TILE_B;
        #pragma unroll
        for (int t = 0; t < 4; t++) {
            int idx = tid + t * 256;
            int row = idx >> 3, cg = idx & 7;
            CP_ASYNC16(ab + (uint32_t)(row * LDS_ROW + cg * 8) * 2,
                       Ap + (size_t)(mbase + row) * KDIM + kc + cg * 8);
        }
        #pragma unroll
        for (int t = 0; t < 8; t++) {
            int idx = tid + t * 256;
            int row = idx >> 3, cg = idx & 7;
            CP_ASYNC16(bb + (uint32_t)(row * LDS_ROW + cg * 8) * 2,
                       Bp + (size_t)(nblk + row) * KDIM + kc + cg * 8);
        }
    };

    prefetch(0, 0); CP_COMMIT();
    prefetch(1, 1); CP_COMMIT();

    int s = 0;
    for (int c = 0; c < 24; c++) {
        if (c < 23) asm volatile("cp.async.wait_group 1;" ::: "memory");
        else        asm volatile("cp.async.wait_group 0;" ::: "memory");
        __syncthreads();
        if (c + 2 < 24) {
            int sn = s + 2; if (sn >= 3) sn -= 3;
            prefetch(c + 2, sn);
            CP_COMMIT();
        }

        uint32_t ab = smb + s * STAGE_B;
        uint32_t bb = ab + A_TILE_B;
        #pragma unroll
        for (int ks = 0; ks < 4; ks++) {        // four k16 sub-steps in BK=64
            uint32_t a[4][4];
            #pragma unroll
            for (int mt = 0; mt < 4; mt++) {
                int row = warp_m * 64 + mt * 16 + (lane & 15);
                int kg  = ks * 2 + (lane >> 4);
                uint32_t ad = ab + (uint32_t)(row * LDS_ROW + kg * 8) * 2;
                LDSM4(a[mt][0], a[mt][1], a[mt][2], a[mt][3], ad);
            }
            uint32_t b[8][2];
            #pragma unroll
            for (int np = 0; np < 4; np++) {    // each x4 covers two n8 tiles
                int row = warp_n * 64 + np * 16 + (lane & 7) + (lane >> 4) * 8;
                int kg  = ks * 2 + ((lane >> 3) & 1);
                uint32_t bd = bb + (uint32_t)(row * LDS_ROW + kg * 8) * 2;
                LDSM4(b[2*np][0], b[2*np][1], b[2*np+1][0], b[2*np+1][1], bd);
            }
            #pragma unroll
            for (int mt = 0; mt < 4; mt++)
                #pragma unroll
                for (int nt = 0; nt < 8; nt++)
                    MMA16816(acc[mt][nt], a[mt], b[nt]);
        }
        if (++s >= 3) s -= 3;
    }

    // epilogue: bias + elu+1 -> g_q / g_k (whole 256-col block is q or k)
    const bool isq = (nblk < C_);
    float* outp = isq ? g_q : g_k;
    int cb = nblk - (isq ? 0 : C_);
    #pragma unroll
    for (int mt = 0; mt < 4; mt++) {
        int mrow = mbase + warp_m * 64 + mt * 16 + (lane >> 2);
        #pragma unroll
        for (int nt = 0; nt < 8; nt++) {
            int ncol = warp_n * 64 + nt * 8 + (lane & 3) * 2;  // 0..255 in block
            float b0 = bias[nblk + ncol], b1 = bias[nblk + ncol + 1];
            float v0 = acc[mt][nt][0] + b0;
            float v1 = acc[mt][nt][1] + b1;
            float v2 = acc[mt][nt][2] + b0;
            float v3 = acc[mt][nt][3] + b1;
            float2 o01, o23;
            o01.x = v0 > 0.f ? v0 + 1.f : expf(v0);
            o01.y = v1 > 0.f ? v1 + 1.f : expf(v1);
            o23.x = v2 > 0.f ? v2 + 1.f : expf(v2);
            o23.y = v3 > 0.f ? v3 + 1.f : expf(v3);
            *(float2*)(outp + (size_t)mrow * C_ + cb + ncol) = o01;
            *(float2*)(outp + (size_t)(mrow + 8) * C_ + cb + ncol) = o23;
        }
    }
}

// ============================================================
// kv partials: per (b,h,chunk): kv += k_rope^T v ; ksum += k
// ============================================================
__global__ __launch_bounds__(256) void kv_k(const float* __restrict__ X) {
    int bh = blockIdx.x;              // B_*H_
    int b  = bh >> 4;
    int h  = bh & 15;
    int chunk = blockIdx.y;
    int tid = threadIdx.x;
    int p  = tid & 15;                // pair within head
    int r0 = tid >> 4;                // 0..15

    __shared__ __align__(16) float kr[64][32];
    __shared__ __align__(16) float vs[64][32];
    __shared__ float sred[16][32];

    float4 acc = make_float4(0.f, 0.f, 0.f, 0.f);
    float se = 0.f, so = 0.f;
    int d  = tid >> 3;                // 0..31
    int e0 = (tid & 7) * 4;

    for (int sub = 0; sub < CHUNK; sub += 64) {
        int nb = chunk * CHUNK + sub;
        #pragma unroll
        for (int s = 0; s < 4; s++) {
            int r = r0 + s * 16;
            int n = nb + r;
            size_t base = (size_t)(b * N_ + n) * C_ + h * 32 + 2 * p;
            float2 kp = *(const float2*)(g_k + base);
            float2 cs = g_cs[n * 256 + h * 16 + p];
            se += kp.x; so += kp.y;
            float2 krr = make_float2(kp.x * cs.x - kp.y * cs.y,
                                     kp.x * cs.y + kp.y * cs.x);
            *(float2*)(&kr[r][2 * p]) = krr;
            *(float2*)(&vs[r][2 * p]) = *(const float2*)(X + base);
        }
        __syncthreads();
        #pragma unroll 8
        for (int r = 0; r < 64; r++) {
            float a = kr[r][d];
            float4 v = *(const float4*)(&vs[r][e0]);
            acc.x += a * v.x; acc.y += a * v.y;
            acc.z += a * v.z; acc.w += a * v.w;
        }
        __syncthreads();
    }

    float* kvp = g_kvp + ((size_t)chunk * B_ * H_ + bh) * 1024;
    *(float4*)(kvp + d * 32 + e0) = acc;

    sred[r0][2 * p]     = se;
    sred[r0][2 * p + 1] = so;
    __syncthreads();
    if (tid < 32) {
        float s = 0.f;
        #pragma unroll
        for (int i = 0; i < 16; i++) s += sred[i][tid];
        g_ksp[((size_t)chunk * B_ * H_ + bh) * 32 + tid] = s;
    }
}

// ============================================================
// deterministic reduce of partials, scale by 1/N
// ============================================================
__global__ void kvreduce_k() {
    int i = blockIdx.x * 256 + threadIdx.x;  // B*H*1024 = 65536
    float s = 0.f;
    #pragma unroll
    for (int c = 0; c < NCHUNK; c++) s += g_kvp[(size_t)c * B_ * H_ * 1024 + i];
    g_kv[i] = s * (1.f / N_);
    if (i < B_ * H_ * 32) {
        float t = 0.f;
        #pragma unroll
        for (int c = 0; c < NCHUNK; c++) t += g_ksp[(size_t)c * B_ * H_ * 32 + i];
        g_km[i] = t * (1.f / N_);
    }
}

// ============================================================
// out = (q_rope @ kv) * z + lepe  — 3 barriers per 32-row tile,
// kv in registers (fixed head/channel per thread), parallel z.
// ============================================================
__global__ __launch_bounds__(256) void out_k(
    const float* __restrict__ X, const float* __restrict__ lw,
    const float* __restrict__ lb, float* __restrict__ out)
{
    int tile = blockIdx.x;    // N_/32
    int b    = blockIdx.y;
    int half = blockIdx.z;    // 0 or 1 (8 heads each)
    int tid  = threadIdx.x;

    __shared__ float qs[32][257];    // unrotated q (this half)
    __shared__ float qrs[32][257];   // rope(q)
    __shared__ float kms[256];
    __shared__ float zs[32][8];

    int hl = tid >> 5;        // local head 0..7
    int e  = tid & 31;
    int head = half * 8 + hl;
    int c = half * 256 + tid; // global channel

    // kv column for this (head, e) into registers
    float kvr[32];
    const float* kvp = g_kv + ((size_t)(b * 16 + head)) * 1024 + e;
    #pragma unroll
    for (int dd = 0; dd < 32; dd++) kvr[dd] = kvp[dd * 32];

    kms[tid] = g_km[b * 512 + half * 256 + tid];
    float w0 = lw[c * 3 + 0], w1 = lw[c * 3 + 1], w2 = lw[c * 3 + 2];
    float lbc = lb[c];

    // phase 1: load 32 q rows (this half), rope into smem
    int pr = tid & 127;       // pair index within half (0..127)
    int rh = tid >> 7;        // 0/1
    #pragma unroll 4
    for (int i = 0; i < 16; i++) {
        int r = i * 2 + rh;
        int n = tile * 32 + r;
        float2 qp = *(const float2*)(g_q + (size_t)(b * N_ + n) * C_ + half * 256 + 2 * pr);
        float2 cs = g_cs[n * 256 + half * 128 + pr];
        qs[r][2 * pr]      = qp.x;
        qs[r][2 * pr + 1]  = qp.y;
        qrs[r][2 * pr]     = qp.x * cs.x - qp.y * cs.y;
        qrs[r][2 * pr + 1] = qp.x * cs.y + qp.y * cs.x;
    }
    __syncthreads();

    // phase 2: z for all (row, head) in parallel; lanes map rows (conflict-free)
    {
        int h2 = tid >> 5, r2 = tid & 31;
        float dot = 0.f;
        #pragma unroll
        for (int dd = 0; dd < 32; dd++) dot += qs[r2][h2 * 32 + dd] * kms[h2 * 32 + dd];
        zs[r2][h2] = 1.f / (dot + 1e-6f);
    }
    __syncthreads();

    // phase 3: outputs + fused LePE conv
    for (int r = 0; r < 32; r++) {
        int n = tile * 32 + r;
        size_t row = (size_t)(b * N_ + n) * C_;
        float a0 = 0.f;
        #pragma unroll
        for (int dd = 0; dd < 32; dd++)
            a0 += qrs[r][hl * 32 + dd] * kvr[dd];
        a0 *= zs[r][hl];

        float xc = X[row + c];
        float xm = (n > 0)      ? X[row - C_ + c] : 0.f;
        float xp = (n < N_ - 1) ? X[row + C_ + c] : 0.f;
        out[row + c] = a0 + xm * w0 + xc * w1 + xp * w2 + lbc;
    }
}

// ============================================================
extern "C" void kernel_launch(void* const* d_in, const int* in_sizes, int n_in,
                              void* d_out, int out_size) {
    const float* x   = (const float*)d_in[0];
    const float* Wqk = (const float*)d_in[1];
    const float* bqk = (const float*)d_in[2];
    const float* lw  = (const float*)d_in[3];
    const float* lb  = (const float*)d_in[4];
    float* out = (float*)d_out;

    cudaFuncSetAttribute(gemm_hmma_k, cudaFuncAttributeMaxDynamicSharedMemorySize, GEMM_SMEM);

    rope_table_k<<<N_ * 256 / 256, 256>>>();
    split_x_k<<<M_ * KDIM / 4 / 256, 256>>>(x);
    split_wt_k<<<NOUT * KDIM / 256, 256>>>(Wqk);
    gemm_hmma_k<<<dim3(NOUT / 256, M_ / 128), 256, GEMM_SMEM>>>(bqk);
    kv_k<<<dim3(B_ * H_, NCHUNK), 256>>>(x);
    kvreduce_k<<<B_ * H_ * 1024 / 256, 256>>>();
    out_k<<<dim3(N_ / 32, B_, 2), 256>>>(x, lw, lb, out);
}

// round 12
// speedup vs baseline: 1.0263x; 1.0263x over previous
#include <cuda_runtime.h>
#include <cuda_bf16.h>
#include <cstdint>
#include <stdint.h>
#include <math.h>

#define B_    4
#define N_    4096
#define C_    512
#define H_    16
#define D_    32
#define M_    (B_*N_)      // 16384
#define KDIM  512
#define NOUT  1024
#define NCHUNK 8
#define CHUNK (N_/NCHUNK)  // 512

// -------- scratch (device globals; no allocations allowed) --------
__device__ float  g_q[M_*C_];                      // elu(q)+1
__device__ float  g_k[M_*C_];                      // elu(k)+1
__device__ float2 g_cs[N_*256];                    // rope cos/sin table
__device__ float  g_kvp[NCHUNK*B_*H_*D_*D_];       // partial kv
__device__ float  g_ksp[NCHUNK*B_*H_*D_];          // partial k sums
__device__ float  g_kv[B_*H_*D_*D_];               // kv (scaled by 1/N)
__device__ float  g_km[B_*H_*D_];                  // kmean
// bf16x3 split operands for the tensor-core GEMM
__device__ __nv_bfloat16 g_xhi[M_*KDIM];
__device__ __nv_bfloat16 g_xlo[M_*KDIM];
__device__ __nv_bfloat16 g_wthi[NOUT*KDIM];        // W^T [n][k]
__device__ __nv_bfloat16 g_wtlo[NOUT*KDIM];

// ============================================================
// helpers (base-ISA only: ldmatrix / mma.sync / cp.async)
// ============================================================
__device__ __forceinline__ uint32_t smem_u32(const void* p) {
    uint32_t a;
    asm("{ .reg .u64 t; cvta.to.shared.u64 t, %1; cvt.u32.u64 %0, t; }"
        : "=r"(a) : "l"(p));
    return a;
}
#define CP_ASYNC16(dst, src) \
    asm volatile("cp.async.cg.shared.global [%0], [%1], 16;" :: "r"(dst), "l"(src))
#define CP_COMMIT() asm volatile("cp.async.commit_group;" ::: "memory")
#define LDSM4(r0, r1, r2, r3, addr) \
    asm volatile("ldmatrix.sync.aligned.m8n8.x4.shared.b16 {%0,%1,%2,%3}, [%4];" \
        : "=r"(r0), "=r"(r1), "=r"(r2), "=r"(r3) : "r"(addr))
#define MMA16816(d, a, b) \
    asm volatile("mma.sync.aligned.m16n8k16.row.col.f32.bf16.bf16.f32 " \
        "{%0,%1,%2,%3}, {%4,%5,%6,%7}, {%8,%9}, {%0,%1,%2,%3};" \
        : "+f"((d)[0]), "+f"((d)[1]), "+f"((d)[2]), "+f"((d)[3]) \
        : "r"((a)[0]), "r"((a)[1]), "r"((a)[2]), "r"((a)[3]), \
          "r"((b)[0]), "r"((b)[1]))

// ============================================================
// RoPE table: emulate JAX fp32 theta & ang, accurate sincos.
// ============================================================
__global__ void rope_table_k() {
    int idx = blockIdx.x * 256 + threadIdx.x;     // N_*256 entries
    int n = idx >> 8;
    int j = idx & 255;
    double theta_d = exp((double)j * (-9.210340371976184 / 256.0));
    float  theta   = (float)theta_d;
    float  ang     = (float)n * theta;            // fp32 multiply, like JAX
    double a = (double)ang;
    double kq = rint(a * 0.15915494309189535);    // 1/(2*pi)
    double r  = fma(-kq, 6.283185307179586, a);
    float s, c;
    sincosf((float)r, &s, &c);
    g_cs[idx] = make_float2(c, s);
}

// ============================================================
// bf16 hi/lo splits
// ============================================================
__global__ void split_x_k(const float* __restrict__ X) {
    int i = blockIdx.x * 256 + threadIdx.x;       // float4 index, M_*KDIM/4 total
    float4 v = ((const float4*)X)[i];
    __nv_bfloat16 h0 = __float2bfloat16(v.x), h1 = __float2bfloat16(v.y);
    __nv_bfloat16 h2 = __float2bfloat16(v.z), h3 = __float2bfloat16(v.w);
    __nv_bfloat16 l0 = __float2bfloat16(v.x - __bfloat162float(h0));
    __nv_bfloat16 l1 = __float2bfloat16(v.y - __bfloat162float(h1));
    __nv_bfloat16 l2 = __float2bfloat16(v.z - __bfloat162float(h2));
    __nv_bfloat16 l3 = __float2bfloat16(v.w - __bfloat162float(h3));
    __nv_bfloat162* ph = (__nv_bfloat162*)(g_xhi + 4 * (size_t)i);
    __nv_bfloat162* pl = (__nv_bfloat162*)(g_xlo + 4 * (size_t)i);
    ph[0] = __nv_bfloat162(h0, h1); ph[1] = __nv_bfloat162(h2, h3);
    pl[0] = __nv_bfloat162(l0, l1); pl[1] = __nv_bfloat162(l2, l3);
}

__global__ void split_wt_k(const float* __restrict__ W) {
    int i = blockIdx.x * 256 + threadIdx.x;       // NOUT*KDIM total
    int n = i >> 9, k = i & 511;
    float v = W[(size_t)k * NOUT + n];
    __nv_bfloat16 h = __float2bfloat16(v);
    g_wthi[i] = h;
    g_wtlo[i] = __float2bfloat16(v - __bfloat162float(h));
}

// ============================================================
// HMMA GEMM: qk = x @ Wqk + b via bf16x3 (K_eff = 1536),
// CTA tile 128x128, 4 warps (2x2), warp tile 64x64, BK=64,
// 3-stage cp.async pipeline, 2 CTAs/SM.
// ============================================================
#define BK       64
#define LDS_ROW  72                    // 64 halves + 8 pad
#define TILE_B   (128 * LDS_ROW * 2)   // 18432 per operand tile
#define STAGE_B  (2 * TILE_B)          // 36864 per stage
#define GEMM_SMEM (3 * STAGE_B)        // 110592

__global__ __launch_bounds__(128, 2) void gemm_hmma_k(const float* __restrict__ bias)
{
    extern __shared__ __align__(16) char sm[];
    uint32_t smb = smem_u32(sm);

    int tid = threadIdx.x;
    int lane = tid & 31, wid = tid >> 5;
    int warp_m = wid & 1;         // 2 x 64 rows
    int warp_n = wid >> 1;        // 2 x 64 cols
    int mbase = blockIdx.y * 128;
    int nblk  = blockIdx.x * 128;

    float acc[4][8][4];
    #pragma unroll
    for (int i = 0; i < 4; i++)
        #pragma unroll
        for (int j = 0; j < 8; j++)
            #pragma unroll
            for (int r = 0; r < 4; r++) acc[i][j][r] = 0.f;

    // 24 chunks of BK=64; pass = c>>3 in {0:(hi,hi), 1:(hi,lo), 2:(lo,hi)}
    auto prefetch = [&](int c, int s) {
        int pass = c >> 3;
        int kc   = (c & 7) * BK;
        const __nv_bfloat16* Ap = (pass < 2) ? g_xhi : g_xlo;
        const __nv_bfloat16* Bp = (pass == 1) ? g_wtlo : g_wthi;
        uint32_t ab = smb + s * STAGE_B;
        uint32_t bb = ab + TILE_B;
        #pragma unroll
        for (int t = 0; t < 8; t++) {
            int idx = tid + t * 128;
            int row = idx >> 3, cg = idx & 7;
            CP_ASYNC16(ab + (uint32_t)(row * LDS_ROW + cg * 8) * 2,
                       Ap + (size_t)(mbase + row) * KDIM + kc + cg * 8);
        }
        #pragma unroll
        for (int t = 0; t < 8; t++) {
            int idx = tid + t * 128;
            int row = idx >> 3, cg = idx & 7;
            CP_ASYNC16(bb + (uint32_t)(row * LDS_ROW + cg * 8) * 2,
                       Bp + (size_t)(nblk + row) * KDIM + kc + cg * 8);
        }
    };

    prefetch(0, 0); CP_COMMIT();
    prefetch(1, 1); CP_COMMIT();

    int s = 0;
    for (int c = 0; c < 24; c++) {
        if (c < 23) asm volatile("cp.async.wait_group 1;" ::: "memory");
        else        asm volatile("cp.async.wait_group 0;" ::: "memory");
        __syncthreads();
        if (c + 2 < 24) {
            int sn = s + 2; if (sn >= 3) sn -= 3;
            prefetch(c + 2, sn);
            CP_COMMIT();
        }

        uint32_t ab = smb + s * STAGE_B;
        uint32_t bb = ab + TILE_B;
        #pragma unroll
        for (int ks = 0; ks < 4; ks++) {        // four k16 sub-steps in BK=64
            uint32_t a[4][4];
            #pragma unroll
            for (int mt = 0; mt < 4; mt++) {
                int row = warp_m * 64 + mt * 16 + (lane & 15);
                int kg  = ks * 2 + (lane >> 4);
                uint32_t ad = ab + (uint32_t)(row * LDS_ROW + kg * 8) * 2;
                LDSM4(a[mt][0], a[mt][1], a[mt][2], a[mt][3], ad);
            }
            uint32_t b[8][2];
            #pragma unroll
            for (int np = 0; np < 4; np++) {    // each x4 covers two n8 tiles
                int row = warp_n * 64 + np * 16 + (lane & 7) + (lane >> 4) * 8;
                int kg  = ks * 2 + ((lane >> 3) & 1);
                uint32_t bd = bb + (uint32_t)(row * LDS_ROW + kg * 8) * 2;
                LDSM4(b[2*np][0], b[2*np][1], b[2*np+1][0], b[2*np+1][1], bd);
            }
            #pragma unroll
            for (int mt = 0; mt < 4; mt++)
                #pragma unroll
                for (int nt = 0; nt < 8; nt++)
                    MMA16816(acc[mt][nt], a[mt], b[nt]);
        }
        if (++s >= 3) s -= 3;
    }

    // epilogue: bias + elu+1 -> g_q / g_k (whole 128-col block is q or k)
    const bool isq = (nblk < C_);
    float* outp = isq ? g_q : g_k;
    int cb = nblk - (isq ? 0 : C_);
    #pragma unroll
    for (int mt = 0; mt < 4; mt++) {
        int mrow = mbase + warp_m * 64 + mt * 16 + (lane >> 2);
        #pragma unroll
        for (int nt = 0; nt < 8; nt++) {
            int ncol = warp_n * 64 + nt * 8 + (lane & 3) * 2;  // 0..127 in block
            float b0 = bias[nblk + ncol], b1 = bias[nblk + ncol + 1];
            float v0 = acc[mt][nt][0] + b0;
            float v1 = acc[mt][nt][1] + b1;
            float v2 = acc[mt][nt][2] + b0;
            float v3 = acc[mt][nt][3] + b1;
            float2 o01, o23;
            o01.x = v0 > 0.f ? v0 + 1.f : expf(v0);
            o01.y = v1 > 0.f ? v1 + 1.f : expf(v1);
            o23.x = v2 > 0.f ? v2 + 1.f : expf(v2);
            o23.y = v3 > 0.f ? v3 + 1.f : expf(v3);
            *(float2*)(outp + (size_t)mrow * C_ + cb + ncol) = o01;
            *(float2*)(outp + (size_t)(mrow + 8) * C_ + cb + ncol) = o23;
        }
    }
}

// ============================================================
// kv partials: per (b,h,chunk): kv += k_rope^T v ; ksum += k
// ============================================================
__global__ __launch_bounds__(256) void kv_k(const float* __restrict__ X) {
    int bh = blockIdx.x;              // B_*H_
    int b  = bh >> 4;
    int h  = bh & 15;
    int chunk = blockIdx.y;
    int tid = threadIdx.x;
    int p  = tid & 15;                // pair within head
    int r0 = tid >> 4;                // 0..15

    __shared__ __align__(16) float kr[64][32];
    __shared__ __align__(16) float vs[64][32];
    __shared__ float sred[16][32];

    float4 acc = make_float4(0.f, 0.f, 0.f, 0.f);
    float se = 0.f, so = 0.f;
    int d  = tid >> 3;                // 0..31
    int e0 = (tid & 7) * 4;

    for (int sub = 0; sub < CHUNK; sub += 64) {
        int nb = chunk * CHUNK + sub;
        #pragma unroll
        for (int s = 0; s < 4; s++) {
            int r = r0 + s * 16;
            int n = nb + r;
            size_t base = (size_t)(b * N_ + n) * C_ + h * 32 + 2 * p;
            float2 kp = *(const float2*)(g_k + base);
            float2 cs = g_cs[n * 256 + h * 16 + p];
            se += kp.x; so += kp.y;
            float2 krr = make_float2(kp.x * cs.x - kp.y * cs.y,
                                     kp.x * cs.y + kp.y * cs.x);
            *(float2*)(&kr[r][2 * p]) = krr;
            *(float2*)(&vs[r][2 * p]) = *(const float2*)(X + base);
        }
        __syncthreads();
        #pragma unroll 8
        for (int r = 0; r < 64; r++) {
            float a = kr[r][d];
            float4 v = *(const float4*)(&vs[r][e0]);
            acc.x += a * v.x; acc.y += a * v.y;
            acc.z += a * v.z; acc.w += a * v.w;
        }
        __syncthreads();
    }

    float* kvp = g_kvp + ((size_t)chunk * B_ * H_ + bh) * 1024;
    *(float4*)(kvp + d * 32 + e0) = acc;

    sred[r0][2 * p]     = se;
    sred[r0][2 * p + 1] = so;
    __syncthreads();
    if (tid < 32) {
        float s = 0.f;
        #pragma unroll
        for (int i = 0; i < 16; i++) s += sred[i][tid];
        g_ksp[((size_t)chunk * B_ * H_ + bh) * 32 + tid] = s;
    }
}

// ============================================================
// deterministic reduce of partials, scale by 1/N
// ============================================================
__global__ void kvreduce_k() {
    int i = blockIdx.x * 256 + threadIdx.x;  // B*H*1024 = 65536
    float s = 0.f;
    #pragma unroll
    for (int c = 0; c < NCHUNK; c++) s += g_kvp[(size_t)c * B_ * H_ * 1024 + i];
    g_kv[i] = s * (1.f / N_);
    if (i < B_ * H_ * 32) {
        float t = 0.f;
        #pragma unroll
        for (int c = 0; c < NCHUNK; c++) t += g_ksp[(size_t)c * B_ * H_ * 32 + i];
        g_km[i] = t * (1.f / N_);
    }
}

// ============================================================
// out = (q_rope @ kv) * z + lepe  — 3 barriers per 32-row tile,
// kv in registers (fixed head/channel per thread), parallel z.
// ============================================================
__global__ __launch_bounds__(256) void out_k(
    const float* __restrict__ X, const float* __restrict__ lw,
    const float* __restrict__ lb, float* __restrict__ out)
{
    int tile = blockIdx.x;    // N_/32
    int b    = blockIdx.y;
    int half = blockIdx.z;    // 0 or 1 (8 heads each)
    int tid  = threadIdx.x;

    __shared__ float qs[32][257];    // unrotated q (this half)
    __shared__ float qrs[32][257];   // rope(q)
    __shared__ float kms[256];
    __shared__ float zs[32][8];

    int hl = tid >> 5;        // local head 0..7
    int e  = tid & 31;
    int head = half * 8 + hl;
    int c = half * 256 + tid; // global channel

    // kv column for this (head, e) into registers
    float kvr[32];
    const float* kvp = g_kv + ((size_t)(b * 16 + head)) * 1024 + e;
    #pragma unroll
    for (int dd = 0; dd < 32; dd++) kvr[dd] = kvp[dd * 32];

    kms[tid] = g_km[b * 512 + half * 256 + tid];
    float w0 = lw[c * 3 + 0], w1 = lw[c * 3 + 1], w2 = lw[c * 3 + 2];
    float lbc = lb[c];

    // phase 1: load 32 q rows (this half), rope into smem
    int pr = tid & 127;       // pair index within half (0..127)
    int rh = tid >> 7;        // 0/1
    #pragma unroll 4
    for (int i = 0; i < 16; i++) {
        int r = i * 2 + rh;
        int n = tile * 32 + r;
        float2 qp = *(const float2*)(g_q + (size_t)(b * N_ + n) * C_ + half * 256 + 2 * pr);
        float2 cs = g_cs[n * 256 + half * 128 + pr];
        qs[r][2 * pr]      = qp.x;
        qs[r][2 * pr + 1]  = qp.y;
        qrs[r][2 * pr]     = qp.x * cs.x - qp.y * cs.y;
        qrs[r][2 * pr + 1] = qp.x * cs.y + qp.y * cs.x;
    }
    __syncthreads();

    // phase 2: z for all (row, head) in parallel; lanes map rows (conflict-free)
    {
        int h2 = tid >> 5, r2 = tid & 31;
        float dot = 0.f;
        #pragma unroll
        for (int dd = 0; dd < 32; dd++) dot += qs[r2][h2 * 32 + dd] * kms[h2 * 32 + dd];
        zs[r2][h2] = 1.f / (dot + 1e-6f);
    }
    __syncthreads();

    // phase 3: outputs + fused LePE conv
    for (int r = 0; r < 32; r++) {
        int n = tile * 32 + r;
        size_t row = (size_t)(b * N_ + n) * C_;
        float a0 = 0.f;
        #pragma unroll
        for (int dd = 0; dd < 32; dd++)
            a0 += qrs[r][hl * 32 + dd] * kvr[dd];
        a0 *= zs[r][hl];

        float xc = X[row + c];
        float xm = (n > 0)      ? X[row - C_ + c] : 0.f;
        float xp = (n < N_ - 1) ? X[row + C_ + c] : 0.f;
        out[row + c] = a0 + xm * w0 + xc * w1 + xp * w2 + lbc;
    }
}

// ============================================================
extern "C" void kernel_launch(void* const* d_in, const int* in_sizes, int n_in,
                              void* d_out, int out_size) {
    const float* x   = (const float*)d_in[0];
    const float* Wqk = (const float*)d_in[1];
    const float* bqk = (const float*)d_in[2];
    const float* lw  = (const float*)d_in[3];
    const float* lb  = (const float*)d_in[4];
    float* out = (float*)d_out;

    cudaFuncSetAttribute(gemm_hmma_k, cudaFuncAttributeMaxDynamicSharedMemorySize, GEMM_SMEM);

    rope_table_k<<<N_ * 256 / 256, 256>>>();
    split_x_k<<<M_ * KDIM / 4 / 256, 256>>>(x);
    split_wt_k<<<NOUT * KDIM / 256, 256>>>(Wqk);
    gemm_hmma_k<<<dim3(NOUT / 128, M_ / 128), 128, GEMM_SMEM>>>(bqk);
    kv_k<<<dim3(B_ * H_, NCHUNK), 256>>>(x);
    kvreduce_k<<<B_ * H_ * 1024 / 256, 256>>>();
    out_k<<<dim3(N_ / 32, B_, 2), 256>>>(x, lw, lb, out);
}

// round 14
// speedup vs baseline: 1.2360x; 1.2043x over previous
#include <cuda_runtime.h>
#include <cuda_bf16.h>
#include <cstdint>
#include <stdint.h>
#include <math.h>

#define B_    4
#define N_    4096
#define C_    512
#define H_    16
#define D_    32
#define M_    (B_*N_)      // 16384
#define KDIM  512
#define NOUT  1024
#define NCHUNK 8
#define CHUNK (N_/NCHUNK)  // 512

// -------- scratch (device globals; no allocations allowed) --------
__device__ float  g_q[M_*C_];                      // elu(q)+1
__device__ float  g_k[M_*C_];                      // elu(k)+1
__device__ float2 g_cs[N_*256];                    // rope cos/sin table
__device__ float  g_theta[256];                    // rope theta (fp32, from double exp)
__device__ float  g_kvp[NCHUNK*B_*H_*D_*D_];       // partial kv
__device__ float  g_ksp[NCHUNK*B_*H_*D_];          // partial k sums
__device__ float  g_kv[B_*H_*D_*D_];               // kv (scaled by 1/N)
__device__ float  g_km[B_*H_*D_];                  // kmean
// bf16x3 split operands for the tensor-core GEMM
__device__ __nv_bfloat16 g_xhi[M_*KDIM];
__device__ __nv_bfloat16 g_xlo[M_*KDIM];
__device__ __nv_bfloat16 g_wthi[NOUT*KDIM];        // W^T [n][k]
__device__ __nv_bfloat16 g_wtlo[NOUT*KDIM];

// ============================================================
// helpers (base-ISA only: ldmatrix / mma.sync / cp.async)
// ============================================================
__device__ __forceinline__ uint32_t smem_u32(const void* p) {
    uint32_t a;
    asm("{ .reg .u64 t; cvta.to.shared.u64 t, %1; cvt.u32.u64 %0, t; }"
        : "=r"(a) : "l"(p));
    return a;
}
#define CP_ASYNC16(dst, src) \
    asm volatile("cp.async.cg.shared.global [%0], [%1], 16;" :: "r"(dst), "l"(src))
#define CP_COMMIT() asm volatile("cp.async.commit_group;" ::: "memory")
#define LDSM4(r0, r1, r2, r3, addr) \
    asm volatile("ldmatrix.sync.aligned.m8n8.x4.shared.b16 {%0,%1,%2,%3}, [%4];" \
        : "=r"(r0), "=r"(r1), "=r"(r2), "=r"(r3) : "r"(addr))
#define MMA16816(d, a, b) \
    asm volatile("mma.sync.aligned.m16n8k16.row.col.f32.bf16.bf16.f32 " \
        "{%0,%1,%2,%3}, {%4,%5,%6,%7}, {%8,%9}, {%0,%1,%2,%3};" \
        : "+f"((d)[0]), "+f"((d)[1]), "+f"((d)[2]), "+f"((d)[3]) \
        : "r"((a)[0]), "r"((a)[1]), "r"((a)[2]), "r"((a)[3]), \
          "r"((b)[0]), "r"((b)[1]))

// ============================================================
// theta table: the ONLY double-precision exp, 256 threads total.
// ============================================================
__global__ void theta_k() {
    int j = threadIdx.x;
    double theta_d = exp((double)j * (-9.210340371976184 / 256.0));
    g_theta[j] = (float)theta_d;     // same rounding as before
}

// ============================================================
// RoPE table: fp32 ang (matches JAX), cheap double range-reduce.
// ============================================================
__global__ void rope_table_k() {
    int idx = blockIdx.x * 256 + threadIdx.x;     // N_*256 entries
    int n = idx >> 8;
    int j = idx & 255;
    float theta = g_theta[j];
    float ang   = (float)n * theta;               // fp32 multiply, like JAX
    double a = (double)ang;
    double kq = rint(a * 0.15915494309189535);    // 1/(2*pi)
    double r  = fma(-kq, 6.283185307179586, a);
    float s, c;
    sincosf((float)r, &s, &c);                    // |r| <= pi: accurate
    g_cs[idx] = make_float2(c, s);
}

// ============================================================
// bf16 hi/lo splits
// ============================================================
__global__ void split_x_k(const float* __restrict__ X) {
    int i = blockIdx.x * 256 + threadIdx.x;       // float4 index, M_*KDIM/4 total
    float4 v = ((const float4*)X)[i];
    __nv_bfloat16 h0 = __float2bfloat16(v.x), h1 = __float2bfloat16(v.y);
    __nv_bfloat16 h2 = __float2bfloat16(v.z), h3 = __float2bfloat16(v.w);
    __nv_bfloat16 l0 = __float2bfloat16(v.x - __bfloat162float(h0));
    __nv_bfloat16 l1 = __float2bfloat16(v.y - __bfloat162float(h1));
    __nv_bfloat16 l2 = __float2bfloat16(v.z - __bfloat162float(h2));
    __nv_bfloat16 l3 = __float2bfloat16(v.w - __bfloat162float(h3));
    __nv_bfloat162* ph = (__nv_bfloat162*)(g_xhi + 4 * (size_t)i);
    __nv_bfloat162* pl = (__nv_bfloat162*)(g_xlo + 4 * (size_t)i);
    ph[0] = __nv_bfloat162(h0, h1); ph[1] = __nv_bfloat162(h2, h3);
    pl[0] = __nv_bfloat162(l0, l1); pl[1] = __nv_bfloat162(l2, l3);
}

// W [k][n] -> W^T [n][k] hi/lo via 32x32 smem tile (both sides coalesced)
__global__ __launch_bounds__(256) void split_wt_k(const float* __restrict__ W) {
    __shared__ float tile[32][33];
    int nb = blockIdx.x * 32;       // n tile base
    int kb = blockIdx.y * 32;       // k tile base
    int tx = threadIdx.x & 31;      // inner
    int ty = threadIdx.x >> 5;      // 0..7

    #pragma unroll
    for (int r = 0; r < 4; r++) {
        int k = kb + ty + r * 8;
        tile[ty + r * 8][tx] = W[(size_t)k * NOUT + nb + tx];   // coalesced over n
    }
    __syncthreads();
    #pragma unroll
    for (int r = 0; r < 4; r++) {
        int n = nb + ty + r * 8;
        float v = tile[tx][ty + r * 8];
        __nv_bfloat16 h = __float2bfloat16(v);
        size_t o = (size_t)n * KDIM + kb + tx;                  // coalesced over k
        g_wthi[o] = h;
        g_wtlo[o] = __float2bfloat16(v - __bfloat162float(h));
    }
}

// ============================================================
// HMMA GEMM: qk = x @ Wqk + b via bf16x3 (K_eff = 1536),
// 3-stage cp.async pipeline, BK=64, one barrier per chunk.
// Tile 128x128, 8 warps, warp tile 64x32 (m16n8k16).  [R10 config]
// ============================================================
#define BK      64
#define LDS_ROW 72                  // 64 halves + 8 pad: conflict-free ldmatrix
#define TILE_B  (128 * LDS_ROW * 2) // 18432 bytes per operand tile
#define STAGE_B (2 * TILE_B)        // 36864 per stage
#define GEMM_SMEM (3 * STAGE_B)     // 110592

__global__ __launch_bounds__(256, 2) void gemm_hmma_k(const float* __restrict__ bias)
{
    extern __shared__ __align__(16) char sm[];
    uint32_t smb = smem_u32(sm);

    int tid = threadIdx.x;
    int lane = tid & 31, wid = tid >> 5;
    int warp_m = wid & 1;         // 2 x 64 rows
    int warp_n = wid >> 1;        // 4 x 32 cols
    int mbase = blockIdx.y * 128;
    int nblk  = blockIdx.x * 128;

    float acc[4][4][4];
    #pragma unroll
    for (int i = 0; i < 4; i++)
        #pragma unroll
        for (int j = 0; j < 4; j++)
            #pragma unroll
            for (int r = 0; r < 4; r++) acc[i][j][r] = 0.f;

    // 24 chunks of BK=64; pass = c>>3 in {0:(hi,hi), 1:(hi,lo), 2:(lo,hi)}
    auto prefetch = [&](int c, int s) {
        int pass = c >> 3;
        int kc   = (c & 7) * BK;
        const __nv_bfloat16* Ap = (pass < 2) ? g_xhi : g_xlo;
        const __nv_bfloat16* Bp = (pass == 1) ? g_wtlo : g_wthi;
        uint32_t ab = smb + s * STAGE_B;
        uint32_t bb = ab + TILE_B;
        #pragma unroll
        for (int t = 0; t < 4; t++) {
            int idx = tid + t * 256;
            int row = idx >> 3, cg = idx & 7;
            CP_ASYNC16(ab + (uint32_t)(row * LDS_ROW + cg * 8) * 2,
                       Ap + (size_t)(mbase + row) * KDIM + kc + cg * 8);
        }
        #pragma unroll
        for (int t = 0; t < 4; t++) {
            int idx = tid + t * 256;
            int row = idx >> 3, cg = idx & 7;
            CP_ASYNC16(bb + (uint32_t)(row * LDS_ROW + cg * 8) * 2,
                       Bp + (size_t)(nblk + row) * KDIM + kc + cg * 8);
        }
    };

    prefetch(0, 0); CP_COMMIT();
    prefetch(1, 1); CP_COMMIT();

    int s = 0;
    for (int c = 0; c < 24; c++) {
        if (c < 23) asm volatile("cp.async.wait_group 1;" ::: "memory");
        else        asm volatile("cp.async.wait_group 0;" ::: "memory");
        __syncthreads();
        if (c + 2 < 24) {
            int sn = s + 2; if (sn >= 3) sn -= 3;
            prefetch(c + 2, sn);
            CP_COMMIT();
        }

        uint32_t ab = smb + s * STAGE_B;
        uint32_t bb = ab + TILE_B;
        #pragma unroll
        for (int ks = 0; ks < 4; ks++) {        // four k16 sub-steps in BK=64
            uint32_t a[4][4];
            #pragma unroll
            for (int mt = 0; mt < 4; mt++) {
                int row = warp_m * 64 + mt * 16 + (lane & 15);
                int kg  = ks * 2 + (lane >> 4);
                uint32_t ad = ab + (uint32_t)(row * LDS_ROW + kg * 8) * 2;
                LDSM4(a[mt][0], a[mt][1], a[mt][2], a[mt][3], ad);
            }
            uint32_t b[4][2];
            #pragma unroll
            for (int np = 0; np < 2; np++) {    // each x4 covers two n8 tiles
                int row = warp_n * 32 + np * 16 + (lane & 7) + (lane >> 4) * 8;
                int kg  = ks * 2 + ((lane >> 3) & 1);
                uint32_t bd = bb + (uint32_t)(row * LDS_ROW + kg * 8) * 2;
                LDSM4(b[2*np][0], b[2*np][1], b[2*np+1][0], b[2*np+1][1], bd);
            }
            #pragma unroll
            for (int mt = 0; mt < 4; mt++)
                #pragma unroll
                for (int nt = 0; nt < 4; nt++)
                    MMA16816(acc[mt][nt], a[mt], b[nt]);
        }
        if (++s >= 3) s -= 3;
    }

    // epilogue: bias + elu+1 -> g_q / g_k (whole 128-col block is q or k)
    const bool isq = (nblk < C_);
    float* outp = isq ? g_q : g_k;
    int cb = nblk - (isq ? 0 : C_);
    #pragma unroll
    for (int mt = 0; mt < 4; mt++) {
        int mrow = mbase + warp_m * 64 + mt * 16 + (lane >> 2);
        #pragma unroll
        for (int nt = 0; nt < 4; nt++) {
            int ncol = warp_n * 32 + nt * 8 + (lane & 3) * 2;  // 0..127 in block
            float b0 = bias[nblk + ncol], b1 = bias[nblk + ncol + 1];
            float v0 = acc[mt][nt][0] + b0;
            float v1 = acc[mt][nt][1] + b1;
            float v2 = acc[mt][nt][2] + b0;
            float v3 = acc[mt][nt][3] + b1;
            float2 o01, o23;
            o01.x = v0 > 0.f ? v0 + 1.f : expf(v0);
            o01.y = v1 > 0.f ? v1 + 1.f : expf(v1);
            o23.x = v2 > 0.f ? v2 + 1.f : expf(v2);
            o23.y = v3 > 0.f ? v3 + 1.f : expf(v3);
            *(float2*)(outp + (size_t)mrow * C_ + cb + ncol) = o01;
            *(float2*)(outp + (size_t)(mrow + 8) * C_ + cb + ncol) = o23;
        }
    }
}

// ============================================================
// kv partials: per (b,h,chunk): kv += k_rope^T v ; ksum += k
// ============================================================
__global__ __launch_bounds__(256) void kv_k(const float* __restrict__ X) {
    int bh = blockIdx.x;              // B_*H_
    int b  = bh >> 4;
    int h  = bh & 15;
    int chunk = blockIdx.y;
    int tid = threadIdx.x;
    int p  = tid & 15;                // pair within head
    int r0 = tid >> 4;                // 0..15

    __shared__ __align__(16) float kr[64][32];
    __shared__ __align__(16) float vs[64][32];
    __shared__ float sred[16][32];

    float4 acc = make_float4(0.f, 0.f, 0.f, 0.f);
    float se = 0.f, so = 0.f;
    int d  = tid >> 3;                // 0..31
    int e0 = (tid & 7) * 4;

    for (int sub = 0; sub < CHUNK; sub += 64) {
        int nb = chunk * CHUNK + sub;
        #pragma unroll
        for (int s = 0; s < 4; s++) {
            int r = r0 + s * 16;
            int n = nb + r;
            size_t base = (size_t)(b * N_ + n) * C_ + h * 32 + 2 * p;
            float2 kp = *(const float2*)(g_k + base);
            float2 cs = g_cs[n * 256 + h * 16 + p];
            se += kp.x; so += kp.y;
            float2 krr = make_float2(kp.x * cs.x - kp.y * cs.y,
                                     kp.x * cs.y + kp.y * cs.x);
            *(float2*)(&kr[r][2 * p]) = krr;
            *(float2*)(&vs[r][2 * p]) = *(const float2*)(X + base);
        }
        __syncthreads();
        #pragma unroll 8
        for (int r = 0; r < 64; r++) {
            float a = kr[r][d];
            float4 v = *(const float4*)(&vs[r][e0]);
            acc.x += a * v.x; acc.y += a * v.y;
            acc.z += a * v.z; acc.w += a * v.w;
        }
        __syncthreads();
    }

    float* kvp = g_kvp + ((size_t)chunk * B_ * H_ + bh) * 1024;
    *(float4*)(kvp + d * 32 + e0) = acc;

    sred[r0][2 * p]     = se;
    sred[r0][2 * p + 1] = so;
    __syncthreads();
    if (tid < 32) {
        float s = 0.f;
        #pragma unroll
        for (int i = 0; i < 16; i++) s += sred[i][tid];
        g_ksp[((size_t)chunk * B_ * H_ + bh) * 32 + tid] = s;
    }
}

// ============================================================
// deterministic reduce of partials, scale by 1/N
// ============================================================
__global__ void kvreduce_k() {
    int i = blockIdx.x * 256 + threadIdx.x;  // B*H*1024 = 65536
    float s = 0.f;
    #pragma unroll
    for (int c = 0; c < NCHUNK; c++) s += g_kvp[(size_t)c * B_ * H_ * 1024 + i];
    g_kv[i] = s * (1.f / N_);
    if (i < B_ * H_ * 32) {
        float t = 0.f;
        #pragma unroll
        for (int c = 0; c < NCHUNK; c++) t += g_ksp[(size_t)c * B_ * H_ * 32 + i];
        g_km[i] = t * (1.f / N_);
    }
}

// ============================================================
// out = (q_rope @ kv) * z + lepe  — 3 barriers per 32-row tile,
// kv in registers (fixed head/channel per thread), parallel z.
// ============================================================
__global__ __launch_bounds__(256) void out_k(
    const float* __restrict__ X, const float* __restrict__ lw,
    const float* __restrict__ lb, float* __restrict__ out)
{
    int tile = blockIdx.x;    // N_/32
    int b    = blockIdx.y;
    int half = blockIdx.z;    // 0 or 1 (8 heads each)
    int tid  = threadIdx.x;

    __shared__ float qs[32][257];    // unrotated q (this half)
    __shared__ float qrs[32][257];   // rope(q)
    __shared__ float kms[256];
    __shared__ float zs[32][8];

    int hl = tid >> 5;        // local head 0..7
    int e  = tid & 31;
    int head = half * 8 + hl;
    int c = half * 256 + tid; // global channel

    // kv column for this (head, e) into registers
    float kvr[32];
    const float* kvp = g_kv + ((size_t)(b * 16 + head)) * 1024 + e;
    #pragma unroll
    for (int dd = 0; dd < 32; dd++) kvr[dd] = kvp[dd * 32];

    kms[tid] = g_km[b * 512 + half * 256 + tid];
    float w0 = lw[c * 3 + 0], w1 = lw[c * 3 + 1], w2 = lw[c * 3 + 2];
    float lbc = lb[c];

    // phase 1: load 32 q rows (this half), rope into smem
    int pr = tid & 127;       // pair index within half (0..127)
    int rh = tid >> 7;        // 0/1
    #pragma unroll 4
    for (int i = 0; i < 16; i++) {
        int r = i * 2 + rh;
        int n = tile * 32 + r;
        float2 qp = *(const float2*)(g_q + (size_t)(b * N_ + n) * C_ + half * 256 + 2 * pr);
        float2 cs = g_cs[n * 256 + half * 128 + pr];
        qs[r][2 * pr]      = qp.x;
        qs[r][2 * pr + 1]  = qp.y;
        qrs[r][2 * pr]     = qp.x * cs.x - qp.y * cs.y;
        qrs[r][2 * pr + 1] = qp.x * cs.y + qp.y * cs.x;
    }
    __syncthreads();

    // phase 2: z for all (row, head) in parallel; lanes map rows (conflict-free)
    {
        int h2 = tid >> 5, r2 = tid & 31;
        float dot = 0.f;
        #pragma unroll
        for (int dd = 0; dd < 32; dd++) dot += qs[r2][h2 * 32 + dd] * kms[h2 * 32 + dd];
        zs[r2][h2] = 1.f / (dot + 1e-6f);
    }
    __syncthreads();

    // phase 3: outputs + fused LePE conv
    for (int r = 0; r < 32; r++) {
        int n = tile * 32 + r;
        size_t row = (size_t)(b * N_ + n) * C_;
        float a0 = 0.f;
        #pragma unroll
        for (int dd = 0; dd < 32; dd++)
            a0 += qrs[r][hl * 32 + dd] * kvr[dd];
        a0 *= zs[r][hl];

        float xc = X[row + c];
        float xm = (n > 0)      ? X[row - C_ + c] : 0.f;
        float xp = (n < N_ - 1) ? X[row + C_ + c] : 0.f;
        out[row + c] = a0 + xm * w0 + xc * w1 + xp * w2 + lbc;
    }
}

// ============================================================
extern "C" void kernel_launch(void* const* d_in, const int* in_sizes, int n_in,
                              void* d_out, int out_size) {
    const float* x   = (const float*)d_in[0];
    const float* Wqk = (const float*)d_in[1];
    const float* bqk = (const float*)d_in[2];
    const float* lw  = (const float*)d_in[3];
    const float* lb  = (const float*)d_in[4];
    float* out = (float*)d_out;

    cudaFuncSetAttribute(gemm_hmma_k, cudaFuncAttributeMaxDynamicSharedMemorySize, GEMM_SMEM);

    theta_k<<<1, 256>>>();
    rope_table_k<<<N_ * 256 / 256, 256>>>();
    split_x_k<<<M_ * KDIM / 4 / 256, 256>>>(x);
    split_wt_k<<<dim3(NOUT / 32, KDIM / 32), 256>>>(Wqk);
    gemm_hmma_k<<<dim3(NOUT / 128, M_ / 128), 256, GEMM_SMEM>>>(bqk);
    kv_k<<<dim3(B_ * H_, NCHUNK), 256>>>(x);
    kvreduce_k<<<B_ * H_ * 1024 / 256, 256>>>();
    out_k<<<dim3(N_ / 32, B_, 2), 256>>>(x, lw, lb, out);
}

// round 15
// speedup vs baseline: 1.8086x; 1.4632x over previous
#include <cuda_runtime.h>
#include <cuda_fp16.h>
#include <cstdint>
#include <stdint.h>
#include <math.h>

#define B_    4
#define N_    4096
#define C_    512
#define H_    16
#define D_    32
#define M_    (B_*N_)      // 16384
#define KDIM  512
#define NOUT  1024
#define NCHUNK 8
#define CHUNK (N_/NCHUNK)  // 512

// -------- scratch (device globals; no allocations allowed) --------
__device__ float  g_q[M_*C_];                      // elu(q)+1
__device__ float  g_k[M_*C_];                      // elu(k)+1
__device__ float2 g_cs[N_*256];                    // rope cos/sin table
__device__ float  g_theta[256];                    // rope theta (fp32, from double exp)
__device__ float  g_kvp[NCHUNK*B_*H_*D_*D_];       // partial kv
__device__ float  g_ksp[NCHUNK*B_*H_*D_];          // partial k sums
__device__ float  g_kv[B_*H_*D_*D_];               // kv (scaled by 1/N)
__device__ float  g_km[B_*H_*D_];                  // kmean
// fp16 operands for the single-pass tensor-core GEMM
__device__ __half g_xh[M_*KDIM];
__device__ __half g_wth[NOUT*KDIM];                // W^T [n][k]

// ============================================================
// helpers (base-ISA only: ldmatrix / mma.sync / cp.async)
// ============================================================
__device__ __forceinline__ uint32_t smem_u32(const void* p) {
    uint32_t a;
    asm("{ .reg .u64 t; cvta.to.shared.u64 t, %1; cvt.u32.u64 %0, t; }"
        : "=r"(a) : "l"(p));
    return a;
}
#define CP_ASYNC16(dst, src) \
    asm volatile("cp.async.cg.shared.global [%0], [%1], 16;" :: "r"(dst), "l"(src))
#define CP_COMMIT() asm volatile("cp.async.commit_group;" ::: "memory")
#define LDSM4(r0, r1, r2, r3, addr) \
    asm volatile("ldmatrix.sync.aligned.m8n8.x4.shared.b16 {%0,%1,%2,%3}, [%4];" \
        : "=r"(r0), "=r"(r1), "=r"(r2), "=r"(r3) : "r"(addr))
#define MMA16816F16(d, a, b) \
    asm volatile("mma.sync.aligned.m16n8k16.row.col.f32.f16.f16.f32 " \
        "{%0,%1,%2,%3}, {%4,%5,%6,%7}, {%8,%9}, {%0,%1,%2,%3};" \
        : "+f"((d)[0]), "+f"((d)[1]), "+f"((d)[2]), "+f"((d)[3]) \
        : "r"((a)[0]), "r"((a)[1]), "r"((a)[2]), "r"((a)[3]), \
          "r"((b)[0]), "r"((b)[1]))

// ============================================================
// theta table: the ONLY double-precision exp, 256 threads total.
// ============================================================
__global__ void theta_k() {
    int j = threadIdx.x;
    double theta_d = exp((double)j * (-9.210340371976184 / 256.0));
    g_theta[j] = (float)theta_d;     // same rounding as before
}

// ============================================================
// RoPE table: fp32 ang (matches JAX), cheap double range-reduce.
// ============================================================
__global__ void rope_table_k() {
    int idx = blockIdx.x * 256 + threadIdx.x;     // N_*256 entries
    int n = idx >> 8;
    int j = idx & 255;
    float theta = g_theta[j];
    float ang   = (float)n * theta;               // fp32 multiply, like JAX
    double a = (double)ang;
    double kq = rint(a * 0.15915494309189535);    // 1/(2*pi)
    double r  = fma(-kq, 6.283185307179586, a);
    float s, c;
    sincosf((float)r, &s, &c);                    // |r| <= pi: accurate
    g_cs[idx] = make_float2(c, s);
}

// ============================================================
// fp16 conversion of X (coalesced both sides)
// ============================================================
__global__ void split_x_k(const float* __restrict__ X) {
    int i = blockIdx.x * 256 + threadIdx.x;       // float4 index, M_*KDIM/4 total
    float4 v = ((const float4*)X)[i];
    __half2* ph = (__half2*)(g_xh + 4 * (size_t)i);
    ph[0] = __floats2half2_rn(v.x, v.y);
    ph[1] = __floats2half2_rn(v.z, v.w);
}

// W [k][n] -> W^T [n][k] fp16 via 32x32 smem tile (both sides coalesced)
__global__ __launch_bounds__(256) void split_wt_k(const float* __restrict__ W) {
    __shared__ float tile[32][33];
    int nb = blockIdx.x * 32;       // n tile base
    int kb = blockIdx.y * 32;       // k tile base
    int tx = threadIdx.x & 31;      // inner
    int ty = threadIdx.x >> 5;      // 0..7

    #pragma unroll
    for (int r = 0; r < 4; r++) {
        int k = kb + ty + r * 8;
        tile[ty + r * 8][tx] = W[(size_t)k * NOUT + nb + tx];   // coalesced over n
    }
    __syncthreads();
    #pragma unroll
    for (int r = 0; r < 4; r++) {
        int n = nb + ty + r * 8;
        g_wth[(size_t)n * KDIM + kb + tx] = __float2half_rn(tile[tx][ty + r * 8]);
    }
}

// ============================================================
// HMMA GEMM: qk = x @ Wqk + b, single-pass fp16 (K = 512),
// 3-stage cp.async pipeline, BK=64, one barrier per chunk.
// Tile 128x128, 8 warps, warp tile 64x32 (m16n8k16).
// ============================================================
#define BK      64
#define LDS_ROW 72                  // 64 halves + 8 pad: conflict-free ldmatrix
#define TILE_B  (128 * LDS_ROW * 2) // 18432 bytes per operand tile
#define STAGE_B (2 * TILE_B)        // 36864 per stage
#define GEMM_SMEM (3 * STAGE_B)     // 110592

__global__ __launch_bounds__(256, 2) void gemm_hmma_k(const float* __restrict__ bias)
{
    extern __shared__ __align__(16) char sm[];
    uint32_t smb = smem_u32(sm);

    int tid = threadIdx.x;
    int lane = tid & 31, wid = tid >> 5;
    int warp_m = wid & 1;         // 2 x 64 rows
    int warp_n = wid >> 1;        // 4 x 32 cols
    int mbase = blockIdx.y * 128;
    int nblk  = blockIdx.x * 128;

    float acc[4][4][4];
    #pragma unroll
    for (int i = 0; i < 4; i++)
        #pragma unroll
        for (int j = 0; j < 4; j++)
            #pragma unroll
            for (int r = 0; r < 4; r++) acc[i][j][r] = 0.f;

    // 8 chunks of BK=64 over K=512
    auto prefetch = [&](int c, int s) {
        int kc = c * BK;
        uint32_t ab = smb + s * STAGE_B;
        uint32_t bb = ab + TILE_B;
        #pragma unroll
        for (int t = 0; t < 4; t++) {
            int idx = tid + t * 256;
            int row = idx >> 3, cg = idx & 7;
            CP_ASYNC16(ab + (uint32_t)(row * LDS_ROW + cg * 8) * 2,
                       g_xh + (size_t)(mbase + row) * KDIM + kc + cg * 8);
        }
        #pragma unroll
        for (int t = 0; t < 4; t++) {
            int idx = tid + t * 256;
            int row = idx >> 3, cg = idx & 7;
            CP_ASYNC16(bb + (uint32_t)(row * LDS_ROW + cg * 8) * 2,
                       g_wth + (size_t)(nblk + row) * KDIM + kc + cg * 8);
        }
    };

    prefetch(0, 0); CP_COMMIT();
    prefetch(1, 1); CP_COMMIT();

    int s = 0;
    for (int c = 0; c < 8; c++) {
        if (c < 7) asm volatile("cp.async.wait_group 1;" ::: "memory");
        else       asm volatile("cp.async.wait_group 0;" ::: "memory");
        __syncthreads();
        if (c + 2 < 8) {
            int sn = s + 2; if (sn >= 3) sn -= 3;
            prefetch(c + 2, sn);
            CP_COMMIT();
        }

        uint32_t ab = smb + s * STAGE_B;
        uint32_t bb = ab + TILE_B;
        #pragma unroll
        for (int ks = 0; ks < 4; ks++) {        // four k16 sub-steps in BK=64
            uint32_t a[4][4];
            #pragma unroll
            for (int mt = 0; mt < 4; mt++) {
                int row = warp_m * 64 + mt * 16 + (lane & 15);
                int kg  = ks * 2 + (lane >> 4);
                uint32_t ad = ab + (uint32_t)(row * LDS_ROW + kg * 8) * 2;
                LDSM4(a[mt][0], a[mt][1], a[mt][2], a[mt][3], ad);
            }
            uint32_t b[4][2];
            #pragma unroll
            for (int np = 0; np < 2; np++) {    // each x4 covers two n8 tiles
                int row = warp_n * 32 + np * 16 + (lane & 7) + (lane >> 4) * 8;
                int kg  = ks * 2 + ((lane >> 3) & 1);
                uint32_t bd = bb + (uint32_t)(row * LDS_ROW + kg * 8) * 2;
                LDSM4(b[2*np][0], b[2*np][1], b[2*np+1][0], b[2*np+1][1], bd);
            }
            #pragma unroll
            for (int mt = 0; mt < 4; mt++)
                #pragma unroll
                for (int nt = 0; nt < 4; nt++)
                    MMA16816F16(acc[mt][nt], a[mt], b[nt]);
        }
        if (++s >= 3) s -= 3;
    }

    // epilogue: bias + elu+1 -> g_q / g_k (whole 128-col block is q or k)
    const bool isq = (nblk < C_);
    float* outp = isq ? g_q : g_k;
    int cb = nblk - (isq ? 0 : C_);
    #pragma unroll
    for (int mt = 0; mt < 4; mt++) {
        int mrow = mbase + warp_m * 64 + mt * 16 + (lane >> 2);
        #pragma unroll
        for (int nt = 0; nt < 4; nt++) {
            int ncol = warp_n * 32 + nt * 8 + (lane & 3) * 2;  // 0..127 in block
            float b0 = bias[nblk + ncol], b1 = bias[nblk + ncol + 1];
            float v0 = acc[mt][nt][0] + b0;
            float v1 = acc[mt][nt][1] + b1;
            float v2 = acc[mt][nt][2] + b0;
            float v3 = acc[mt][nt][3] + b1;
            float2 o01, o23;
            o01.x = v0 > 0.f ? v0 + 1.f : expf(v0);
            o01.y = v1 > 0.f ? v1 + 1.f : expf(v1);
            o23.x = v2 > 0.f ? v2 + 1.f : expf(v2);
            o23.y = v3 > 0.f ? v3 + 1.f : expf(v3);
            *(float2*)(outp + (size_t)mrow * C_ + cb + ncol) = o01;
            *(float2*)(outp + (size_t)(mrow + 8) * C_ + cb + ncol) = o23;
        }
    }
}

// ============================================================
// kv partials: per (b,h,chunk): kv += k_rope^T v ; ksum += k
// ============================================================
__global__ __launch_bounds__(256) void kv_k(const float* __restrict__ X) {
    int bh = blockIdx.x;              // B_*H_
    int b  = bh >> 4;
    int h  = bh & 15;
    int chunk = blockIdx.y;
    int tid = threadIdx.x;
    int p  = tid & 15;                // pair within head
    int r0 = tid >> 4;                // 0..15

    __shared__ __align__(16) float kr[64][32];
    __shared__ __align__(16) float vs[64][32];
    __shared__ float sred[16][32];

    float4 acc = make_float4(0.f, 0.f, 0.f, 0.f);
    float se = 0.f, so = 0.f;
    int d  = tid >> 3;                // 0..31
    int e0 = (tid & 7) * 4;

    for (int sub = 0; sub < CHUNK; sub += 64) {
        int nb = chunk * CHUNK + sub;
        #pragma unroll
        for (int s = 0; s < 4; s++) {
            int r = r0 + s * 16;
            int n = nb + r;
            size_t base = (size_t)(b * N_ + n) * C_ + h * 32 + 2 * p;
            float2 kp = *(const float2*)(g_k + base);
            float2 cs = g_cs[n * 256 + h * 16 + p];
            se += kp.x; so += kp.y;
            float2 krr = make_float2(kp.x * cs.x - kp.y * cs.y,
                                     kp.x * cs.y + kp.y * cs.x);
            *(float2*)(&kr[r][2 * p]) = krr;
            *(float2*)(&vs[r][2 * p]) = *(const float2*)(X + base);
        }
        __syncthreads();
        #pragma unroll 8
        for (int r = 0; r < 64; r++) {
            float a = kr[r][d];
            float4 v = *(const float4*)(&vs[r][e0]);
            acc.x += a * v.x; acc.y += a * v.y;
            acc.z += a * v.z; acc.w += a * v.w;
        }
        __syncthreads();
    }

    float* kvp = g_kvp + ((size_t)chunk * B_ * H_ + bh) * 1024;
    *(float4*)(kvp + d * 32 + e0) = acc;

    sred[r0][2 * p]     = se;
    sred[r0][2 * p + 1] = so;
    __syncthreads();
    if (tid < 32) {
        float s = 0.f;
        #pragma unroll
        for (int i = 0; i < 16; i++) s += sred[i][tid];
        g_ksp[((size_t)chunk * B_ * H_ + bh) * 32 + tid] = s;
    }
}

// ============================================================
// deterministic reduce of partials, scale by 1/N
// ============================================================
__global__ void kvreduce_k() {
    int i = blockIdx.x * 256 + threadIdx.x;  // B*H*1024 = 65536
    float s = 0.f;
    #pragma unroll
    for (int c = 0; c < NCHUNK; c++) s += g_kvp[(size_t)c * B_ * H_ * 1024 + i];
    g_kv[i] = s * (1.f / N_);
    if (i < B_ * H_ * 32) {
        float t = 0.f;
        #pragma unroll
        for (int c = 0; c < NCHUNK; c++) t += g_ksp[(size_t)c * B_ * H_ * 32 + i];
        g_km[i] = t * (1.f / N_);
    }
}

// ============================================================
// out = (q_rope @ kv) * z + lepe  — 3 barriers per 32-row tile,
// kv in registers (fixed head/channel per thread), parallel z.
// ============================================================
__global__ __launch_bounds__(256) void out_k(
    const float* __restrict__ X, const float* __restrict__ lw,
    const float* __restrict__ lb, float* __restrict__ out)
{
    int tile = blockIdx.x;    // N_/32
    int b    = blockIdx.y;
    int half = blockIdx.z;    // 0 or 1 (8 heads each)
    int tid  = threadIdx.x;

    __shared__ float qs[32][257];    // unrotated q (this half)
    __shared__ float qrs[32][257];   // rope(q)
    __shared__ float kms[256];
    __shared__ float zs[32][8];

    int hl = tid >> 5;        // local head 0..7
    int e  = tid & 31;
    int head = half * 8 + hl;
    int c = half * 256 + tid; // global channel

    // kv column for this (head, e) into registers
    float kvr[32];
    const float* kvp = g_kv + ((size_t)(b * 16 + head)) * 1024 + e;
    #pragma unroll
    for (int dd = 0; dd < 32; dd++) kvr[dd] = kvp[dd * 32];

    kms[tid] = g_km[b * 512 + half * 256 + tid];
    float w0 = lw[c * 3 + 0], w1 = lw[c * 3 + 1], w2 = lw[c * 3 + 2];
    float lbc = lb[c];

    // phase 1: load 32 q rows (this half), rope into smem
    int pr = tid & 127;       // pair index within half (0..127)
    int rh = tid >> 7;        // 0/1
    #pragma unroll 4
    for (int i = 0; i < 16; i++) {
        int r = i * 2 + rh;
        int n = tile * 32 + r;
        float2 qp = *(const float2*)(g_q + (size_t)(b * N_ + n) * C_ + half * 256 + 2 * pr);
        float2 cs = g_cs[n * 256 + half * 128 + pr];
        qs[r][2 * pr]      = qp.x;
        qs[r][2 * pr + 1]  = qp.y;
        qrs[r][2 * pr]     = qp.x * cs.x - qp.y * cs.y;
        qrs[r][2 * pr + 1] = qp.x * cs.y + qp.y * cs.x;
    }
    __syncthreads();

    // phase 2: z for all (row, head) in parallel; lanes map rows (conflict-free)
    {
        int h2 = tid >> 5, r2 = tid & 31;
        float dot = 0.f;
        #pragma unroll
        for (int dd = 0; dd < 32; dd++) dot += qs[r2][h2 * 32 + dd] * kms[h2 * 32 + dd];
        zs[r2][h2] = 1.f / (dot + 1e-6f);
    }
    __syncthreads();

    // phase 3: outputs + fused LePE conv
    for (int r = 0; r < 32; r++) {
        int n = tile * 32 + r;
        size_t row = (size_t)(b * N_ + n) * C_;
        float a0 = 0.f;
        #pragma unroll
        for (int dd = 0; dd < 32; dd++)
            a0 += qrs[r][hl * 32 + dd] * kvr[dd];
        a0 *= zs[r][hl];

        float xc = X[row + c];
        float xm = (n > 0)      ? X[row - C_ + c] : 0.f;
        float xp = (n < N_ - 1) ? X[row + C_ + c] : 0.f;
        out[row + c] = a0 + xm * w0 + xc * w1 + xp * w2 + lbc;
    }
}

// ============================================================
extern "C" void kernel_launch(void* const* d_in, const int* in_sizes, int n_in,
                              void* d_out, int out_size) {
    const float* x   = (const float*)d_in[0];
    const float* Wqk = (const float*)d_in[1];
    const float* bqk = (const float*)d_in[2];
    const float* lw  = (const float*)d_in[3];
    const float* lb  = (const float*)d_in[4];
    float* out = (float*)d_out;

    cudaFuncSetAttribute(gemm_hmma_k, cudaFuncAttributeMaxDynamicSharedMemorySize, GEMM_SMEM);

    theta_k<<<1, 256>>>();
    rope_table_k<<<N_ * 256 / 256, 256>>>();
    split_x_k<<<M_ * KDIM / 4 / 256, 256>>>(x);
    split_wt_k<<<dim3(NOUT / 32, KDIM / 32), 256>>>(Wqk);
    gemm_hmma_k<<<dim3(NOUT / 128, M_ / 128), 256, GEMM_SMEM>>>(bqk);
    kv_k<<<dim3(B_ * H_, NCHUNK), 256>>>(x);
    kvreduce_k<<<B_ * H_ * 1024 / 256, 256>>>();
    out_k<<<dim3(N_ / 32, B_, 2), 256>>>(x, lw, lb, out);
}

// round 16
// speedup vs baseline: 2.1254x; 1.1752x over previous
#include <cuda_runtime.h>
#include <cuda_fp16.h>
#include <cstdint>
#include <stdint.h>
#include <math.h>

#define B_    4
#define N_    4096
#define C_    512
#define H_    16
#define D_    32
#define M_    (B_*N_)      // 16384
#define KDIM  512
#define NOUT  1024
#define NCHUNK 8
#define CHUNK (N_/NCHUNK)  // 512

// -------- scratch (device globals; no allocations allowed) --------
__device__ __half g_qh[M_*C_];                     // elu(q)+1, fp16
__device__ __half g_kh[M_*C_];                     // elu(k)+1, fp16
__device__ float2 g_cs[N_*256];                    // rope cos/sin table
__device__ float  g_theta[256];                    // rope theta (fp32, from double exp)
__device__ float  g_kvp[NCHUNK*B_*H_*D_*D_];       // partial kv
__device__ float  g_ksp[NCHUNK*B_*H_*D_];          // partial k sums
__device__ float  g_kv[B_*H_*D_*D_];               // kv (scaled by 1/N)
__device__ float  g_km[B_*H_*D_];                  // kmean
// fp16 operands for the single-pass tensor-core GEMM (also v for kv_k)
__device__ __half g_xh[M_*KDIM];
__device__ __half g_wth[NOUT*KDIM];                // W^T [n][k]

// ============================================================
// helpers (base-ISA only: ldmatrix / mma.sync / cp.async)
// ============================================================
__device__ __forceinline__ uint32_t smem_u32(const void* p) {
    uint32_t a;
    asm("{ .reg .u64 t; cvta.to.shared.u64 t, %1; cvt.u32.u64 %0, t; }"
        : "=r"(a) : "l"(p));
    return a;
}
#define CP_ASYNC16(dst, src) \
    asm volatile("cp.async.cg.shared.global [%0], [%1], 16;" :: "r"(dst), "l"(src))
#define CP_COMMIT() asm volatile("cp.async.commit_group;" ::: "memory")
#define LDSM4(r0, r1, r2, r3, addr) \
    asm volatile("ldmatrix.sync.aligned.m8n8.x4.shared.b16 {%0,%1,%2,%3}, [%4];" \
        : "=r"(r0), "=r"(r1), "=r"(r2), "=r"(r3) : "r"(addr))
#define MMA16816F16(d, a, b) \
    asm volatile("mma.sync.aligned.m16n8k16.row.col.f32.f16.f16.f32 " \
        "{%0,%1,%2,%3}, {%4,%5,%6,%7}, {%8,%9}, {%0,%1,%2,%3};" \
        : "+f"((d)[0]), "+f"((d)[1]), "+f"((d)[2]), "+f"((d)[3]) \
        : "r"((a)[0]), "r"((a)[1]), "r"((a)[2]), "r"((a)[3]), \
          "r"((b)[0]), "r"((b)[1]))

// ============================================================
// fp16 conversion of X (coalesced both sides); block 0 also
// computes the 256-entry theta table (the only DP exp).
// ============================================================
__global__ void split_x_k(const float* __restrict__ X) {
    if (blockIdx.x == 0) {
        int j = threadIdx.x;
        double theta_d = exp((double)j * (-9.210340371976184 / 256.0));
        g_theta[j] = (float)theta_d;
    }
    int i = blockIdx.x * 256 + threadIdx.x;       // float4 index, M_*KDIM/4 total
    float4 v = ((const float4*)X)[i];
    __half2* ph = (__half2*)(g_xh + 4 * (size_t)i);
    ph[0] = __floats2half2_rn(v.x, v.y);
    ph[1] = __floats2half2_rn(v.z, v.w);
}

// ============================================================
// RoPE table: fp32 ang (matches JAX), cheap double range-reduce.
// ============================================================
__global__ void rope_table_k() {
    int idx = blockIdx.x * 256 + threadIdx.x;     // N_*256 entries
    int n = idx >> 8;
    int j = idx & 255;
    float theta = g_theta[j];
    float ang   = (float)n * theta;               // fp32 multiply, like JAX
    double a = (double)ang;
    double kq = rint(a * 0.15915494309189535);    // 1/(2*pi)
    double r  = fma(-kq, 6.283185307179586, a);
    float s, c;
    sincosf((float)r, &s, &c);                    // |r| <= pi: accurate
    g_cs[idx] = make_float2(c, s);
}

// W [k][n] -> W^T [n][k] fp16 via 32x32 smem tile (both sides coalesced)
__global__ __launch_bounds__(256) void split_wt_k(const float* __restrict__ W) {
    __shared__ float tile[32][33];
    int nb = blockIdx.x * 32;       // n tile base
    int kb = blockIdx.y * 32;       // k tile base
    int tx = threadIdx.x & 31;      // inner
    int ty = threadIdx.x >> 5;      // 0..7

    #pragma unroll
    for (int r = 0; r < 4; r++) {
        int k = kb + ty + r * 8;
        tile[ty + r * 8][tx] = W[(size_t)k * NOUT + nb + tx];   // coalesced over n
    }
    __syncthreads();
    #pragma unroll
    for (int r = 0; r < 4; r++) {
        int n = nb + ty + r * 8;
        g_wth[(size_t)n * KDIM + kb + tx] = __float2half_rn(tile[tx][ty + r * 8]);
    }
}

// ============================================================
// HMMA GEMM: qk = x @ Wqk + b, single-pass fp16 (K = 512),
// 3-stage cp.async pipeline, BK=64, one barrier per chunk.
// Tile 128x128, 8 warps, warp tile 64x32 (m16n8k16).
// Epilogue: bias + elu+1, fp16 stores.
// ============================================================
#define BK      64
#define LDS_ROW 72                  // 64 halves + 8 pad: conflict-free ldmatrix
#define TILE_B  (128 * LDS_ROW * 2) // 18432 bytes per operand tile
#define STAGE_B (2 * TILE_B)        // 36864 per stage
#define GEMM_SMEM (3 * STAGE_B)     // 110592

__global__ __launch_bounds__(256, 2) void gemm_hmma_k(const float* __restrict__ bias)
{
    extern __shared__ __align__(16) char sm[];
    uint32_t smb = smem_u32(sm);

    int tid = threadIdx.x;
    int lane = tid & 31, wid = tid >> 5;
    int warp_m = wid & 1;         // 2 x 64 rows
    int warp_n = wid >> 1;        // 4 x 32 cols
    int mbase = blockIdx.y * 128;
    int nblk  = blockIdx.x * 128;

    float acc[4][4][4];
    #pragma unroll
    for (int i = 0; i < 4; i++)
        #pragma unroll
        for (int j = 0; j < 4; j++)
            #pragma unroll
            for (int r = 0; r < 4; r++) acc[i][j][r] = 0.f;

    // 8 chunks of BK=64 over K=512
    auto prefetch = [&](int c, int s) {
        int kc = c * BK;
        uint32_t ab = smb + s * STAGE_B;
        uint32_t bb = ab + TILE_B;
        #pragma unroll
        for (int t = 0; t < 4; t++) {
            int idx = tid + t * 256;
            int row = idx >> 3, cg = idx & 7;
            CP_ASYNC16(ab + (uint32_t)(row * LDS_ROW + cg * 8) * 2,
                       g_xh + (size_t)(mbase + row) * KDIM + kc + cg * 8);
        }
        #pragma unroll
        for (int t = 0; t < 4; t++) {
            int idx = tid + t * 256;
            int row = idx >> 3, cg = idx & 7;
            CP_ASYNC16(bb + (uint32_t)(row * LDS_ROW + cg * 8) * 2,
                       g_wth + (size_t)(nblk + row) * KDIM + kc + cg * 8);
        }
    };

    prefetch(0, 0); CP_COMMIT();
    prefetch(1, 1); CP_COMMIT();

    int s = 0;
    for (int c = 0; c < 8; c++) {
        if (c < 7) asm volatile("cp.async.wait_group 1;" ::: "memory");
        else       asm volatile("cp.async.wait_group 0;" ::: "memory");
        __syncthreads();
        if (c + 2 < 8) {
            int sn = s + 2; if (sn >= 3) sn -= 3;
            prefetch(c + 2, sn);
            CP_COMMIT();
        }

        uint32_t ab = smb + s * STAGE_B;
        uint32_t bb = ab + TILE_B;
        #pragma unroll
        for (int ks = 0; ks < 4; ks++) {        // four k16 sub-steps in BK=64
            uint32_t a[4][4];
            #pragma unroll
            for (int mt = 0; mt < 4; mt++) {
                int row = warp_m * 64 + mt * 16 + (lane & 15);
                int kg  = ks * 2 + (lane >> 4);
                uint32_t ad = ab + (uint32_t)(row * LDS_ROW + kg * 8) * 2;
                LDSM4(a[mt][0], a[mt][1], a[mt][2], a[mt][3], ad);
            }
            uint32_t b[4][2];
            #pragma unroll
            for (int np = 0; np < 2; np++) {    // each x4 covers two n8 tiles
                int row = warp_n * 32 + np * 16 + (lane & 7) + (lane >> 4) * 8;
                int kg  = ks * 2 + ((lane >> 3) & 1);
                uint32_t bd = bb + (uint32_t)(row * LDS_ROW + kg * 8) * 2;
                LDSM4(b[2*np][0], b[2*np][1], b[2*np+1][0], b[2*np+1][1], bd);
            }
            #pragma unroll
            for (int mt = 0; mt < 4; mt++)
                #pragma unroll
                for (int nt = 0; nt < 4; nt++)
                    MMA16816F16(acc[mt][nt], a[mt], b[nt]);
        }
        if (++s >= 3) s -= 3;
    }

    // epilogue: bias + elu+1 -> g_qh / g_kh (fp16)
    const bool isq = (nblk < C_);
    __half* outp = isq ? g_qh : g_kh;
    int cb = nblk - (isq ? 0 : C_);
    #pragma unroll
    for (int mt = 0; mt < 4; mt++) {
        int mrow = mbase + warp_m * 64 + mt * 16 + (lane >> 2);
        #pragma unroll
        for (int nt = 0; nt < 4; nt++) {
            int ncol = warp_n * 32 + nt * 8 + (lane & 3) * 2;  // 0..127 in block
            float b0 = bias[nblk + ncol], b1 = bias[nblk + ncol + 1];
            float v0 = acc[mt][nt][0] + b0;
            float v1 = acc[mt][nt][1] + b1;
            float v2 = acc[mt][nt][2] + b0;
            float v3 = acc[mt][nt][3] + b1;
            float e0 = v0 > 0.f ? v0 + 1.f : expf(v0);
            float e1 = v1 > 0.f ? v1 + 1.f : expf(v1);
            float e2 = v2 > 0.f ? v2 + 1.f : expf(v2);
            float e3 = v3 > 0.f ? v3 + 1.f : expf(v3);
            *(__half2*)(outp + (size_t)mrow * C_ + cb + ncol) = __floats2half2_rn(e0, e1);
            *(__half2*)(outp + (size_t)(mrow + 8) * C_ + cb + ncol) = __floats2half2_rn(e2, e3);
        }
    }
}

// ============================================================
// kv partials: per (b,h,chunk): kv += k_rope^T v ; ksum += k
// fp16 loads, 2d x 8e register tile, 4 row-slices + smem reduce
// ============================================================
__global__ __launch_bounds__(256) void kv_k() {
    int bh = blockIdx.x;              // B_*H_
    int b  = bh >> 4;
    int h  = bh & 15;
    int chunk = blockIdx.y;
    int tid = threadIdx.x;
    int p  = tid & 15;                // pair within head (load mapping)
    int r0 = tid >> 4;                // 0..15

    __shared__ __align__(16) float kr[64][32];
    __shared__ __align__(16) float vs[64][32];
    __shared__ __align__(16) float red[4][1024];
    __shared__ float sred[16][32];

    // compute mapping: 4 row-slices x (16 d-pairs x 4 e-groups)
    int rs  = tid >> 6;               // row slice 0..3
    int t64 = tid & 63;
    int d0  = ((t64 >> 2) & 15) * 2;  // 2 d values
    int e0  = (t64 & 3) * 8;          // 8 e values

    float acc[16];
    #pragma unroll
    for (int i = 0; i < 16; i++) acc[i] = 0.f;
    float se = 0.f, so = 0.f;

    for (int sub = 0; sub < CHUNK; sub += 64) {
        int nb = chunk * CHUNK + sub;
        #pragma unroll
        for (int s = 0; s < 4; s++) {
            int r = r0 + s * 16;
            int n = nb + r;
            size_t base = (size_t)(b * N_ + n) * C_ + h * 32 + 2 * p;
            float2 kp = __half22float2(*(const __half2*)(g_kh + base));
            float2 vv = __half22float2(*(const __half2*)(g_xh + base));
            float2 cs = g_cs[n * 256 + h * 16 + p];
            se += kp.x; so += kp.y;
            kr[r][2 * p]     = kp.x * cs.x - kp.y * cs.y;
            kr[r][2 * p + 1] = kp.x * cs.y + kp.y * cs.x;
            vs[r][2 * p]     = vv.x;
            vs[r][2 * p + 1] = vv.y;
        }
        __syncthreads();
        #pragma unroll 4
        for (int rr = 0; rr < 16; rr++) {
            int r = rs * 16 + rr;
            float2 kk = *(const float2*)&kr[r][d0];
            float4 v0 = *(const float4*)&vs[r][e0];
            float4 v1 = *(const float4*)&vs[r][e0 + 4];
            acc[0]  += kk.x * v0.x;  acc[1]  += kk.x * v0.y;
            acc[2]  += kk.x * v0.z;  acc[3]  += kk.x * v0.w;
            acc[4]  += kk.x * v1.x;  acc[5]  += kk.x * v1.y;
            acc[6]  += kk.x * v1.z;  acc[7]  += kk.x * v1.w;
            acc[8]  += kk.y * v0.x;  acc[9]  += kk.y * v0.y;
            acc[10] += kk.y * v0.z;  acc[11] += kk.y * v0.w;
            acc[12] += kk.y * v1.x;  acc[13] += kk.y * v1.y;
            acc[14] += kk.y * v1.z;  acc[15] += kk.y * v1.w;
        }
        __syncthreads();
    }

    // slice partials -> smem
    #pragma unroll
    for (int i = 0; i < 2; i++)
        #pragma unroll
        for (int j = 0; j < 8; j++)
            red[rs][(d0 + i) * 32 + e0 + j] = acc[i * 8 + j];
    sred[r0][2 * p]     = se;
    sred[r0][2 * p + 1] = so;
    __syncthreads();

    // final reduce across 4 slices: each thread 4 outputs
    {
        int o4 = tid * 4;
        float4 s0 = *(const float4*)&red[0][o4];
        float4 s1 = *(const float4*)&red[1][o4];
        float4 s2 = *(const float4*)&red[2][o4];
        float4 s3 = *(const float4*)&red[3][o4];
        float4 o;
        o.x = s0.x + s1.x + s2.x + s3.x;
        o.y = s0.y + s1.y + s2.y + s3.y;
        o.z = s0.z + s1.z + s2.z + s3.z;
        o.w = s0.w + s1.w + s2.w + s3.w;
        *(float4*)(g_kvp + ((size_t)chunk * B_ * H_ + bh) * 1024 + o4) = o;
    }
    if (tid < 32) {
        float s = 0.f;
        #pragma unroll
        for (int i = 0; i < 16; i++) s += sred[i][tid];
        g_ksp[((size_t)chunk * B_ * H_ + bh) * 32 + tid] = s;
    }
}

// ============================================================
// deterministic reduce of partials, scale by 1/N
// ============================================================
__global__ void kvreduce_k() {
    int i = blockIdx.x * 256 + threadIdx.x;  // B*H*1024 = 65536
    float s = 0.f;
    #pragma unroll
    for (int c = 0; c < NCHUNK; c++) s += g_kvp[(size_t)c * B_ * H_ * 1024 + i];
    g_kv[i] = s * (1.f / N_);
    if (i < B_ * H_ * 32) {
        float t = 0.f;
        #pragma unroll
        for (int c = 0; c < NCHUNK; c++) t += g_ksp[(size_t)c * B_ * H_ * 32 + i];
        g_km[i] = t * (1.f / N_);
    }
}

// ============================================================
// out = (q_rope @ kv) * z + lepe — float4 broadcast dot,
// X register rotation for the conv, fp16 q loads.
// ============================================================
__global__ __launch_bounds__(256) void out_k(
    const float* __restrict__ X, const float* __restrict__ lw,
    const float* __restrict__ lb, float* __restrict__ out)
{
    int tile = blockIdx.x;    // N_/32
    int b    = blockIdx.y;
    int half = blockIdx.z;    // 0 or 1 (8 heads each)
    int tid  = threadIdx.x;

    __shared__ float qs[32][257];    // unrotated q (this half), z phase
    __shared__ __align__(16) float qrs[32][260];   // rope(q), stride mult of 4
    __shared__ float kms[256];
    __shared__ float zs[32][8];

    int hl = tid >> 5;        // local head 0..7
    int e  = tid & 31;
    int head = half * 8 + hl;
    int c = half * 256 + tid; // global channel

    // kv column for this (head, e) into registers
    float kvr[32];
    const float* kvp = g_kv + ((size_t)(b * 16 + head)) * 1024 + e;
    #pragma unroll
    for (int dd = 0; dd < 32; dd++) kvr[dd] = kvp[dd * 32];

    kms[tid] = g_km[b * 512 + half * 256 + tid];
    float w0 = lw[c * 3 + 0], w1 = lw[c * 3 + 1], w2 = lw[c * 3 + 2];
    float lbc = lb[c];

    // phase 1: load 32 q rows (this half), rope into smem
    int pr = tid & 127;       // pair index within half (0..127)
    int rh = tid >> 7;        // 0/1
    #pragma unroll 4
    for (int i = 0; i < 16; i++) {
        int r = i * 2 + rh;
        int n = tile * 32 + r;
        float2 qp = __half22float2(
            *(const __half2*)(g_qh + (size_t)(b * N_ + n) * C_ + half * 256 + 2 * pr));
        float2 cs = g_cs[n * 256 + half * 128 + pr];
        qs[r][2 * pr]      = qp.x;
        qs[r][2 * pr + 1]  = qp.y;
        qrs[r][2 * pr]     = qp.x * cs.x - qp.y * cs.y;
        qrs[r][2 * pr + 1] = qp.x * cs.y + qp.y * cs.x;
    }
    __syncthreads();

    // phase 2: z for all (row, head) in parallel
    {
        int h2 = tid >> 5, r2 = tid & 31;
        float dot = 0.f;
        #pragma unroll
        for (int dd = 0; dd < 32; dd++) dot += qs[r2][h2 * 32 + dd] * kms[h2 * 32 + dd];
        zs[r2][h2] = 1.f / (dot + 1e-6f);
    }
    __syncthreads();

    // phase 3: outputs + fused LePE conv (register rotation on X)
    int n0 = tile * 32;
    size_t rowb = (size_t)(b * N_ + n0) * C_;
    float xm = (n0 > 0) ? X[rowb - C_ + c] : 0.f;
    float xc = X[rowb + c];
    for (int r = 0; r < 32; r++) {
        int n = n0 + r;
        size_t row = rowb + (size_t)r * C_;
        float xp = (n < N_ - 1) ? X[row + C_ + c] : 0.f;

        float a0 = 0.f;
        const float* qp = &qrs[r][hl * 32];   // same addr for whole warp: broadcast
        #pragma unroll
        for (int d4 = 0; d4 < 8; d4++) {
            float4 qv = *(const float4*)(qp + d4 * 4);
            a0 += qv.x * kvr[d4 * 4 + 0] + qv.y * kvr[d4 * 4 + 1]
                + qv.z * kvr[d4 * 4 + 2] + qv.w * kvr[d4 * 4 + 3];
        }
        a0 *= zs[r][hl];

        out[row + c] = a0 + xm * w0 + xc * w1 + xp * w2 + lbc;
        xm = xc; xc = xp;
    }
}

// ============================================================
extern "C" void kernel_launch(void* const* d_in, const int* in_sizes, int n_in,
                              void* d_out, int out_size) {
    const float* x   = (const float*)d_in[0];
    const float* Wqk = (const float*)d_in[1];
    const float* bqk = (const float*)d_in[2];
    const float* lw  = (const float*)d_in[3];
    const float* lb  = (const float*)d_in[4];
    float* out = (float*)d_out;

    cudaFuncSetAttribute(gemm_hmma_k, cudaFuncAttributeMaxDynamicSharedMemorySize, GEMM_SMEM);

    split_x_k<<<M_ * KDIM / 4 / 256, 256>>>(x);     // also writes g_theta (block 0)
    rope_table_k<<<N_ * 256 / 256, 256>>>();
    split_wt_k<<<dim3(NOUT / 32, KDIM / 32), 256>>>(Wqk);
    gemm_hmma_k<<<dim3(NOUT / 128, M_ / 128), 256, GEMM_SMEM>>>(bqk);
    kv_k<<<dim3(B_ * H_, NCHUNK), 256>>>();
    kvreduce_k<<<B_ * H_ * 1024 / 256, 256>>>();
    out_k<<<dim3(N_ / 32, B_, 2), 256>>>(x, lw, lb, out);
}

// round 17
// speedup vs baseline: 2.3069x; 1.0854x over previous
#include <cuda_runtime.h>
#include <cuda_fp16.h>
#include <cstdint>
#include <stdint.h>
#include <math.h>

#define B_    4
#define N_    4096
#define C_    512
#define H_    16
#define D_    32
#define M_    (B_*N_)      // 16384
#define KDIM  512
#define NOUT  1024
#define NCHUNK 8
#define CHUNK (N_/NCHUNK)  // 512

// -------- scratch (device globals; no allocations allowed) --------
__device__ __half g_qh[M_*C_];                     // elu(q)+1, fp16
__device__ __half g_kh[M_*C_];                     // elu(k)+1, fp16
__device__ float2 g_cs[N_*256];                    // rope cos/sin table
__device__ float  g_theta[256];                    // rope theta (fp32, from double exp)
__device__ float  g_kvp[NCHUNK*B_*H_*D_*D_];       // partial kv
__device__ float  g_ksp[NCHUNK*B_*H_*D_];          // partial k sums
__device__ float  g_kv[B_*H_*D_*D_];               // kv (scaled by 1/N)
__device__ float  g_km[B_*H_*D_];                  // kmean
// fp16 operands for the single-pass tensor-core GEMM (also v / lepe src)
__device__ __half g_xh[M_*KDIM];
__device__ __half g_wth[NOUT*KDIM];                // W^T [n][k]

// ============================================================
// helpers (base-ISA only: ldmatrix / mma.sync / cp.async)
// ============================================================
__device__ __forceinline__ uint32_t smem_u32(const void* p) {
    uint32_t a;
    asm("{ .reg .u64 t; cvta.to.shared.u64 t, %1; cvt.u32.u64 %0, t; }"
        : "=r"(a) : "l"(p));
    return a;
}
#define CP_ASYNC16(dst, src) \
    asm volatile("cp.async.cg.shared.global [%0], [%1], 16;" :: "r"(dst), "l"(src))
#define CP_COMMIT() asm volatile("cp.async.commit_group;" ::: "memory")
#define LDSM4(r0, r1, r2, r3, addr) \
    asm volatile("ldmatrix.sync.aligned.m8n8.x4.shared.b16 {%0,%1,%2,%3}, [%4];" \
        : "=r"(r0), "=r"(r1), "=r"(r2), "=r"(r3) : "r"(addr))
#define MMA16816F16(d, a, b) \
    asm volatile("mma.sync.aligned.m16n8k16.row.col.f32.f16.f16.f32 " \
        "{%0,%1,%2,%3}, {%4,%5,%6,%7}, {%8,%9}, {%0,%1,%2,%3};" \
        : "+f"((d)[0]), "+f"((d)[1]), "+f"((d)[2]), "+f"((d)[3]) \
        : "r"((a)[0]), "r"((a)[1]), "r"((a)[2]), "r"((a)[3]), \
          "r"((b)[0]), "r"((b)[1]))

// ============================================================
// fp16 conversion of X (coalesced both sides); block 0 also
// computes the 256-entry theta table (the only DP exp).
// ============================================================
__global__ void split_x_k(const float* __restrict__ X) {
    if (blockIdx.x == 0) {
        int j = threadIdx.x;
        double theta_d = exp((double)j * (-9.210340371976184 / 256.0));
        g_theta[j] = (float)theta_d;
    }
    int i = blockIdx.x * 256 + threadIdx.x;       // float4 index, M_*KDIM/4 total
    float4 v = ((const float4*)X)[i];
    __half2* ph = (__half2*)(g_xh + 4 * (size_t)i);
    ph[0] = __floats2half2_rn(v.x, v.y);
    ph[1] = __floats2half2_rn(v.z, v.w);
}

// ============================================================
// RoPE table: fp32 ang (matches JAX), cheap double range-reduce.
// ============================================================
__global__ void rope_table_k() {
    int idx = blockIdx.x * 256 + threadIdx.x;     // N_*256 entries
    int n = idx >> 8;
    int j = idx & 255;
    float theta = g_theta[j];
    float ang   = (float)n * theta;               // fp32 multiply, like JAX
    double a = (double)ang;
    double kq = rint(a * 0.15915494309189535);    // 1/(2*pi)
    double r  = fma(-kq, 6.283185307179586, a);
    float s, c;
    sincosf((float)r, &s, &c);                    // |r| <= pi: accurate
    g_cs[idx] = make_float2(c, s);
}

// W [k][n] -> W^T [n][k] fp16 via 32x32 smem tile (both sides coalesced)
__global__ __launch_bounds__(256) void split_wt_k(const float* __restrict__ W) {
    __shared__ float tile[32][33];
    int nb = blockIdx.x * 32;       // n tile base
    int kb = blockIdx.y * 32;       // k tile base
    int tx = threadIdx.x & 31;      // inner
    int ty = threadIdx.x >> 5;      // 0..7

    #pragma unroll
    for (int r = 0; r < 4; r++) {
        int k = kb + ty + r * 8;
        tile[ty + r * 8][tx] = W[(size_t)k * NOUT + nb + tx];   // coalesced over n
    }
    __syncthreads();
    #pragma unroll
    for (int r = 0; r < 4; r++) {
        int n = nb + ty + r * 8;
        g_wth[(size_t)n * KDIM + kb + tx] = __float2half_rn(tile[tx][ty + r * 8]);
    }
}

// ============================================================
// HMMA GEMM: qk = x @ Wqk + b, single-pass fp16 (K = 512),
// 5-stage cp.async pipeline, BK=32, wait_group 3 lookahead.
// Tile 128x128, 8 warps, warp tile 64x32 (m16n8k16).
// Epilogue: bias + elu+1, fp16 stores.
// ============================================================
#define BK      32
#define LDS_ROW 40                  // 32 halves + 8 pad: conflict-free ldmatrix
#define TILE_B  (128 * LDS_ROW * 2) // 10240 bytes per operand tile
#define STAGE_B (2 * TILE_B)        // 20480 per stage
#define GEMM_SMEM (5 * STAGE_B)     // 102400

__global__ __launch_bounds__(256, 2) void gemm_hmma_k(const float* __restrict__ bias)
{
    extern __shared__ __align__(16) char sm[];
    uint32_t smb = smem_u32(sm);

    int tid = threadIdx.x;
    int lane = tid & 31, wid = tid >> 5;
    int warp_m = wid & 1;         // 2 x 64 rows
    int warp_n = wid >> 1;        // 4 x 32 cols
    int mbase = blockIdx.y * 128;
    int nblk  = blockIdx.x * 128;

    float acc[4][4][4];
    #pragma unroll
    for (int i = 0; i < 4; i++)
        #pragma unroll
        for (int j = 0; j < 4; j++)
            #pragma unroll
            for (int r = 0; r < 4; r++) acc[i][j][r] = 0.f;

    // 16 chunks of BK=32 over K=512
    auto prefetch = [&](int c, int s) {
        int kc = c * BK;
        uint32_t ab = smb + s * STAGE_B;
        uint32_t bb = ab + TILE_B;
        #pragma unroll
        for (int t = 0; t < 2; t++) {
            int idx = tid + t * 256;
            int row = idx >> 2, cg = idx & 3;    // 32 halves/row = 4 x 16B
            CP_ASYNC16(ab + (uint32_t)(row * LDS_ROW + cg * 8) * 2,
                       g_xh + (size_t)(mbase + row) * KDIM + kc + cg * 8);
        }
        #pragma unroll
        for (int t = 0; t < 2; t++) {
            int idx = tid + t * 256;
            int row = idx >> 2, cg = idx & 3;
            CP_ASYNC16(bb + (uint32_t)(row * LDS_ROW + cg * 8) * 2,
                       g_wth + (size_t)(nblk + row) * KDIM + kc + cg * 8);
        }
    };

    prefetch(0, 0); CP_COMMIT();
    prefetch(1, 1); CP_COMMIT();
    prefetch(2, 2); CP_COMMIT();
    prefetch(3, 3); CP_COMMIT();

    int s = 0;
    for (int c = 0; c < 16; c++) {
        asm volatile("cp.async.wait_group 3;" ::: "memory");
        __syncthreads();
        if (c + 4 < 16) {
            int sn = s + 4; if (sn >= 5) sn -= 5;
            prefetch(c + 4, sn);
        }
        CP_COMMIT();   // always commit (empty groups keep the count uniform)

        uint32_t ab = smb + s * STAGE_B;
        uint32_t bb = ab + TILE_B;
        #pragma unroll
        for (int ks = 0; ks < 2; ks++) {        // two k16 sub-steps in BK=32
            uint32_t a[4][4];
            #pragma unroll
            for (int mt = 0; mt < 4; mt++) {
                int row = warp_m * 64 + mt * 16 + (lane & 15);
                int kg  = ks * 2 + (lane >> 4);
                uint32_t ad = ab + (uint32_t)(row * LDS_ROW + kg * 8) * 2;
                LDSM4(a[mt][0], a[mt][1], a[mt][2], a[mt][3], ad);
            }
            uint32_t b[4][2];
            #pragma unroll
            for (int np = 0; np < 2; np++) {    // each x4 covers two n8 tiles
                int row = warp_n * 32 + np * 16 + (lane & 7) + (lane >> 4) * 8;
                int kg  = ks * 2 + ((lane >> 3) & 1);
                uint32_t bd = bb + (uint32_t)(row * LDS_ROW + kg * 8) * 2;
                LDSM4(b[2*np][0], b[2*np][1], b[2*np+1][0], b[2*np+1][1], bd);
            }
            #pragma unroll
            for (int mt = 0; mt < 4; mt++)
                #pragma unroll
                for (int nt = 0; nt < 4; nt++)
                    MMA16816F16(acc[mt][nt], a[mt], b[nt]);
        }
        if (++s >= 5) s -= 5;
    }

    // epilogue: bias + elu+1 -> g_qh / g_kh (fp16)
    const bool isq = (nblk < C_);
    __half* outp = isq ? g_qh : g_kh;
    int cb = nblk - (isq ? 0 : C_);
    #pragma unroll
    for (int mt = 0; mt < 4; mt++) {
        int mrow = mbase + warp_m * 64 + mt * 16 + (lane >> 2);
        #pragma unroll
        for (int nt = 0; nt < 4; nt++) {
            int ncol = warp_n * 32 + nt * 8 + (lane & 3) * 2;  // 0..127 in block
            float b0 = bias[nblk + ncol], b1 = bias[nblk + ncol + 1];
            float v0 = acc[mt][nt][0] + b0;
            float v1 = acc[mt][nt][1] + b1;
            float v2 = acc[mt][nt][2] + b0;
            float v3 = acc[mt][nt][3] + b1;
            float e0 = v0 > 0.f ? v0 + 1.f : expf(v0);
            float e1 = v1 > 0.f ? v1 + 1.f : expf(v1);
            float e2 = v2 > 0.f ? v2 + 1.f : expf(v2);
            float e3 = v3 > 0.f ? v3 + 1.f : expf(v3);
            *(__half2*)(outp + (size_t)mrow * C_ + cb + ncol) = __floats2half2_rn(e0, e1);
            *(__half2*)(outp + (size_t)(mrow + 8) * C_ + cb + ncol) = __floats2half2_rn(e2, e3);
        }
    }
}

// ============================================================
// kv partials: per (b,h,chunk): kv += k_rope^T v ; ksum += k
// fp16 loads, 2d x 8e register tile, 4 row-slices + smem reduce
// ============================================================
__global__ __launch_bounds__(256) void kv_k() {
    int bh = blockIdx.x;              // B_*H_
    int b  = bh >> 4;
    int h  = bh & 15;
    int chunk = blockIdx.y;
    int tid = threadIdx.x;
    int p  = tid & 15;                // pair within head (load mapping)
    int r0 = tid >> 4;                // 0..15

    __shared__ __align__(16) float kr[64][32];
    __shared__ __align__(16) float vs[64][32];
    __shared__ __align__(16) float red[4][1024];
    __shared__ float sred[16][32];

    // compute mapping: 4 row-slices x (16 d-pairs x 4 e-groups)
    int rs  = tid >> 6;               // row slice 0..3
    int t64 = tid & 63;
    int d0  = ((t64 >> 2) & 15) * 2;  // 2 d values
    int e0  = (t64 & 3) * 8;          // 8 e values

    float acc[16];
    #pragma unroll
    for (int i = 0; i < 16; i++) acc[i] = 0.f;
    float se = 0.f, so = 0.f;

    for (int sub = 0; sub < CHUNK; sub += 64) {
        int nb = chunk * CHUNK + sub;
        #pragma unroll
        for (int s = 0; s < 4; s++) {
            int r = r0 + s * 16;
            int n = nb + r;
            size_t base = (size_t)(b * N_ + n) * C_ + h * 32 + 2 * p;
            float2 kp = __half22float2(*(const __half2*)(g_kh + base));
            float2 vv = __half22float2(*(const __half2*)(g_xh + base));
            float2 cs = g_cs[n * 256 + h * 16 + p];
            se += kp.x; so += kp.y;
            kr[r][2 * p]     = kp.x * cs.x - kp.y * cs.y;
            kr[r][2 * p + 1] = kp.x * cs.y + kp.y * cs.x;
            vs[r][2 * p]     = vv.x;
            vs[r][2 * p + 1] = vv.y;
        }
        __syncthreads();
        #pragma unroll 4
        for (int rr = 0; rr < 16; rr++) {
            int r = rs * 16 + rr;
            float2 kk = *(const float2*)&kr[r][d0];
            float4 v0 = *(const float4*)&vs[r][e0];
            float4 v1 = *(const float4*)&vs[r][e0 + 4];
            acc[0]  += kk.x * v0.x;  acc[1]  += kk.x * v0.y;
            acc[2]  += kk.x * v0.z;  acc[3]  += kk.x * v0.w;
            acc[4]  += kk.x * v1.x;  acc[5]  += kk.x * v1.y;
            acc[6]  += kk.x * v1.z;  acc[7]  += kk.x * v1.w;
            acc[8]  += kk.y * v0.x;  acc[9]  += kk.y * v0.y;
            acc[10] += kk.y * v0.z;  acc[11] += kk.y * v0.w;
            acc[12] += kk.y * v1.x;  acc[13] += kk.y * v1.y;
            acc[14] += kk.y * v1.z;  acc[15] += kk.y * v1.w;
        }
        __syncthreads();
    }

    // slice partials -> smem
    #pragma unroll
    for (int i = 0; i < 2; i++)
        #pragma unroll
        for (int j = 0; j < 8; j++)
            red[rs][(d0 + i) * 32 + e0 + j] = acc[i * 8 + j];
    sred[r0][2 * p]     = se;
    sred[r0][2 * p + 1] = so;
    __syncthreads();

    // final reduce across 4 slices: each thread 4 outputs
    {
        int o4 = tid * 4;
        float4 s0 = *(const float4*)&red[0][o4];
        float4 s1 = *(const float4*)&red[1][o4];
        float4 s2 = *(const float4*)&red[2][o4];
        float4 s3 = *(const float4*)&red[3][o4];
        float4 o;
        o.x = s0.x + s1.x + s2.x + s3.x;
        o.y = s0.y + s1.y + s2.y + s3.y;
        o.z = s0.z + s1.z + s2.z + s3.z;
        o.w = s0.w + s1.w + s2.w + s3.w;
        *(float4*)(g_kvp + ((size_t)chunk * B_ * H_ + bh) * 1024 + o4) = o;
    }
    if (tid < 32) {
        float s = 0.f;
        #pragma unroll
        for (int i = 0; i < 16; i++) s += sred[i][tid];
        g_ksp[((size_t)chunk * B_ * H_ + bh) * 32 + tid] = s;
    }
}

// ============================================================
// deterministic reduce of partials, scale by 1/N
// ============================================================
__global__ void kvreduce_k() {
    int i = blockIdx.x * 256 + threadIdx.x;  // B*H*1024 = 65536
    float s = 0.f;
    #pragma unroll
    for (int c = 0; c < NCHUNK; c++) s += g_kvp[(size_t)c * B_ * H_ * 1024 + i];
    g_kv[i] = s * (1.f / N_);
    if (i < B_ * H_ * 32) {
        float t = 0.f;
        #pragma unroll
        for (int c = 0; c < NCHUNK; c++) t += g_ksp[(size_t)c * B_ * H_ * 32 + i];
        g_km[i] = t * (1.f / N_);
    }
}

// ============================================================
// out = (q_rope @ kv) * z + lepe — float4 broadcast dot,
// fp16 x for LePE (register rotation), fp16 q loads.
// ============================================================
__global__ __launch_bounds__(256) void out_k(
    const float* __restrict__ lw, const float* __restrict__ lb,
    float* __restrict__ out)
{
    int tile = blockIdx.x;    // N_/32
    int b    = blockIdx.y;
    int half = blockIdx.z;    // 0 or 1 (8 heads each)
    int tid  = threadIdx.x;

    __shared__ float qs[32][257];    // unrotated q (this half), z phase
    __shared__ __align__(16) float qrs[32][260];   // rope(q), stride mult of 4
    __shared__ float kms[256];
    __shared__ float zs[32][8];

    int hl = tid >> 5;        // local head 0..7
    int e  = tid & 31;
    int head = half * 8 + hl;
    int c = half * 256 + tid; // global channel

    // kv column for this (head, e) into registers
    float kvr[32];
    const float* kvp = g_kv + ((size_t)(b * 16 + head)) * 1024 + e;
    #pragma unroll
    for (int dd = 0; dd < 32; dd++) kvr[dd] = kvp[dd * 32];

    kms[tid] = g_km[b * 512 + half * 256 + tid];
    float w0 = lw[c * 3 + 0], w1 = lw[c * 3 + 1], w2 = lw[c * 3 + 2];
    float lbc = lb[c];

    // phase 1: load 32 q rows (this half), rope into smem
    int pr = tid & 127;       // pair index within half (0..127)
    int rh = tid >> 7;        // 0/1
    #pragma unroll 4
    for (int i = 0; i < 16; i++) {
        int r = i * 2 + rh;
        int n = tile * 32 + r;
        float2 qp = __half22float2(
            *(const __half2*)(g_qh + (size_t)(b * N_ + n) * C_ + half * 256 + 2 * pr));
        float2 cs = g_cs[n * 256 + half * 128 + pr];
        qs[r][2 * pr]      = qp.x;
        qs[r][2 * pr + 1]  = qp.y;
        qrs[r][2 * pr]     = qp.x * cs.x - qp.y * cs.y;
        qrs[r][2 * pr + 1] = qp.x * cs.y + qp.y * cs.x;
    }
    __syncthreads();

    // phase 2: z for all (row, head) in parallel
    {
        int h2 = tid >> 5, r2 = tid & 31;
        float dot = 0.f;
        #pragma unroll
        for (int dd = 0; dd < 32; dd++) dot += qs[r2][h2 * 32 + dd] * kms[h2 * 32 + dd];
        zs[r2][h2] = 1.f / (dot + 1e-6f);
    }
    __syncthreads();

    // phase 3: outputs + fused LePE conv (register rotation on fp16 x)
    int n0 = tile * 32;
    size_t rowb = (size_t)(b * N_ + n0) * C_;
    float xm = (n0 > 0) ? __half2float(g_xh[rowb - C_ + c]) : 0.f;
    float xc = __half2float(g_xh[rowb + c]);
    for (int r = 0; r < 32; r++) {
        int n = n0 + r;
        size_t row = rowb + (size_t)r * C_;
        float xp = (n < N_ - 1) ? __half2float(g_xh[row + C_ + c]) : 0.f;

        float a0 = 0.f;
        const float* qp = &qrs[r][hl * 32];   // same addr for whole warp: broadcast
        #pragma unroll
        for (int d4 = 0; d4 < 8; d4++) {
            float4 qv = *(const float4*)(qp + d4 * 4);
            a0 += qv.x * kvr[d4 * 4 + 0] + qv.y * kvr[d4 * 4 + 1]
                + qv.z * kvr[d4 * 4 + 2] + qv.w * kvr[d4 * 4 + 3];
        }
        a0 *= zs[r][hl];

        out[row + c] = a0 + xm * w0 + xc * w1 + xp * w2 + lbc;
        xm = xc; xc = xp;
    }
}

// ============================================================
extern "C" void kernel_launch(void* const* d_in, const int* in_sizes, int n_in,
                              void* d_out, int out_size) {
    const float* x   = (const float*)d_in[0];
    const float* Wqk = (const float*)d_in[1];
    const float* bqk = (const float*)d_in[2];
    const float* lw  = (const float*)d_in[3];
    const float* lb  = (const float*)d_in[4];
    float* out = (float*)d_out;

    cudaFuncSetAttribute(gemm_hmma_k, cudaFuncAttributeMaxDynamicSharedMemorySize, GEMM_SMEM);

    split_x_k<<<M_ * KDIM / 4 / 256, 256>>>(x);     // also writes g_theta (block 0)
    rope_table_k<<<N_ * 256 / 256, 256>>>();
    split_wt_k<<<dim3(NOUT / 32, KDIM / 32), 256>>>(Wqk);
    gemm_hmma_k<<<dim3(NOUT / 128, M_ / 128), 256, GEMM_SMEM>>>(bqk);
    kv_k<<<dim3(B_ * H_, NCHUNK), 256>>>();
    kvreduce_k<<<B_ * H_ * 1024 / 256, 256>>>();
    out_k<<<dim3(N_ / 32, B_, 2), 256>>>(lw, lb, out);
}